// round 6
// baseline (speedup 1.0000x reference)
#include <cuda_runtime.h>
#include <cuda_bf16.h>
#include <cstdint>

// Problem constants
#define BB 4
#define TT 1024
#define CC 512
#define HH 8
#define DD 64
#define NROWS (BB*TT)          // 4096
#define C3 (3*CC)              // 1536
#define NEGF (-3.402823466e38f)

// -------- scratch (static device globals; allocation-free) --------
__device__ float g_qkv[(size_t)NROWS*C3];         // 24 MB
__device__ float g_biasT[(size_t)BB*HH*TT*TT];    // 128 MB
__device__ int   g_mask_kind;
__device__ __nv_bfloat16 g_ah[(size_t)NROWS*CC];  // A hi (also attn out hi)
__device__ __nv_bfloat16 g_al[(size_t)NROWS*CC];  // A lo
__device__ __nv_bfloat16 g_wh[(size_t)C3*CC];
__device__ __nv_bfloat16 g_wl[(size_t)C3*CC];
__device__ __nv_bfloat16 g_qh[(size_t)NROWS*CC];
__device__ __nv_bfloat16 g_ql[(size_t)NROWS*CC];
__device__ __nv_bfloat16 g_kh[(size_t)NROWS*CC];
__device__ __nv_bfloat16 g_kl[(size_t)NROWS*CC];
__device__ __nv_bfloat16 g_vh[(size_t)NROWS*CC];
__device__ __nv_bfloat16 g_vl[(size_t)NROWS*CC];

// ================ generic-PTX helpers ================
__device__ __forceinline__ uint32_t smem_u32(const void* p) {
    uint32_t a;
    asm("{ .reg .u64 t; cvta.to.shared.u64 t, %1; cvt.u32.u64 %0, t; }"
        : "=r"(a) : "l"(p));
    return a;
}
#define LDSM_X4(r0, r1, r2, r3, addr) \
    asm volatile("ldmatrix.sync.aligned.m8n8.x4.shared.b16 {%0,%1,%2,%3}, [%4];" \
        : "=r"(r0), "=r"(r1), "=r"(r2), "=r"(r3) : "r"(addr))
#define LDSM_X4_T(r0, r1, r2, r3, addr) \
    asm volatile("ldmatrix.sync.aligned.m8n8.x4.trans.shared.b16 {%0,%1,%2,%3}, [%4];" \
        : "=r"(r0), "=r"(r1), "=r"(r2), "=r"(r3) : "r"(addr))
#define MMA_BF16(d, a, b) \
    asm volatile("mma.sync.aligned.m16n8k16.row.col.f32.bf16.bf16.f32 " \
        "{%0,%1,%2,%3}, {%4,%5,%6,%7}, {%8,%9}, {%0,%1,%2,%3};" \
        : "+f"((d)[0]), "+f"((d)[1]), "+f"((d)[2]), "+f"((d)[3]) \
        : "r"((a)[0]), "r"((a)[1]), "r"((a)[2]), "r"((a)[3]), \
          "r"((b)[0]), "r"((b)[1]))
#define CP_ASYNC16(saddr, gptr) \
    asm volatile("cp.async.cg.shared.global [%0], [%1], 16;" \
        :: "r"(saddr), "l"(gptr))
#define CP_COMMIT() asm volatile("cp.async.commit_group;" ::: "memory")
#define CP_WAIT1()  asm volatile("cp.async.wait_group 1;" ::: "memory")

__device__ __forceinline__ uint32_t pack_bf16x2(float a, float b) {
    __nv_bfloat162 t = __floats2bfloat162_rn(a, b);
    return *reinterpret_cast<uint32_t*>(&t);
}

// fast exp on FMA pipe
__device__ __forceinline__ float fexp(float x) {
    float t = fmaxf(x * 1.4426950408889634f, -126.f);
    float fi = floorf(t);
    float f = t - fi;
    float p = 1.5403530393381609e-4f;
    p = fmaf(p, f, 1.3333558146428443e-3f);
    p = fmaf(p, f, 9.6181291976036826e-3f);
    p = fmaf(p, f, 5.5504108664821580e-2f);
    p = fmaf(p, f, 2.4022650695910071e-1f);
    p = fmaf(p, f, 6.9314718055994531e-1f);
    p = fmaf(p, f, 1.0f);
    int ii = (int)fi;
    return p * __int_as_float((ii + 127) << 23);
}

// ================ LayerNorm core ================
__device__ __forceinline__ float warp_sum(float v) {
    #pragma unroll
    for (int o = 16; o; o >>= 1) v += __shfl_xor_sync(0xffffffffu, v, o);
    return v;
}

__device__ __forceinline__ void ln_core(float4& v, const float* w, const float* b,
                                        int t, float4& o)
{
    float s  = v.x + v.y + v.z + v.w;
    float sq = v.x*v.x + v.y*v.y + v.z*v.z + v.w*v.w;
    s = warp_sum(s); sq = warp_sum(sq);
    __shared__ float sh[8];
    int wid = t >> 5, lid = t & 31;
    if (lid == 0) { sh[wid] = s; sh[4 + wid] = sq; }
    __syncthreads();
    float ts = sh[0] + sh[1] + sh[2] + sh[3];
    float tq = sh[4] + sh[5] + sh[6] + sh[7];
    float mean = ts * (1.f / CC);
    float var  = tq * (1.f / CC) - mean * mean;
    float rstd = rsqrtf(var + 1e-5f);
    float4 wv = *(const float4*)(w + t * 4);
    float4 bv = *(const float4*)(b + t * 4);
    o.x = (v.x - mean) * rstd * wv.x + bv.x;
    o.y = (v.y - mean) * rstd * wv.y + bv.y;
    o.z = (v.z - mean) * rstd * wv.z + bv.z;
    o.w = (v.w - mean) * rstd * wv.w + bv.w;
}

__device__ __forceinline__ void split_store4(float4 o, __nv_bfloat16* hi,
                                             __nv_bfloat16* lo, size_t base)
{
    float vv[4] = {o.x, o.y, o.z, o.w};
    __nv_bfloat16 h[4]; float r[4];
    #pragma unroll
    for (int u = 0; u < 4; u++) { h[u] = __float2bfloat16(vv[u]); r[u] = vv[u] - __bfloat162float(h[u]); }
    *(__nv_bfloat162*)(hi + base)     = __nv_bfloat162{h[0], h[1]};
    *(__nv_bfloat162*)(hi + base + 2) = __nv_bfloat162{h[2], h[3]};
    *(__nv_bfloat162*)(lo + base)     = __floats2bfloat162_rn(r[0], r[1]);
    *(__nv_bfloat162*)(lo + base + 2) = __floats2bfloat162_rn(r[2], r[3]);
}

__global__ void ln_split_kernel(const float* src, const float* __restrict__ w,
                                const float* __restrict__ b,
                                __nv_bfloat16* hi, __nv_bfloat16* lo)
{
    int row = blockIdx.x, t = threadIdx.x;
    float4 v = *(const float4*)(src + (size_t)row * CC + t * 4);
    float4 o;
    ln_core(v, w, b, t, o);
    split_store4(o, hi, lo, (size_t)row * CC + t * 4);
}

__global__ void qkv_post(const float* __restrict__ qkv,
                         const float* __restrict__ qw, const float* __restrict__ qb,
                         const float* __restrict__ kw, const float* __restrict__ kb)
{
    int row = blockIdx.x, t = threadIdx.x;
    const float* rp = qkv + (size_t)row * C3;
    size_t base = (size_t)row * CC + t * 4;
    float4 v = *(const float4*)(rp + t * 4);
    float4 o;
    ln_core(v, qw, qb, t, o);
    o.x *= 0.125f; o.y *= 0.125f; o.z *= 0.125f; o.w *= 0.125f;
    split_store4(o, g_qh, g_ql, base);
    __syncthreads();
    v = *(const float4*)(rp + CC + t * 4);
    ln_core(v, kw, kb, t, o);
    split_store4(o, g_kh, g_kl, base);
    v = *(const float4*)(rp + 2 * CC + t * 4);
    split_store4(v, g_vh, g_vl, base);
}

__global__ void split_kernel(const float* __restrict__ src,
                             __nv_bfloat16* hi, __nv_bfloat16* lo, int n4)
{
    int i = blockIdx.x * blockDim.x + threadIdx.x;
    if (i >= n4) return;
    float4 v = ((const float4*)src)[i];
    split_store4(v, hi, lo, (size_t)i * 4);
}

// ================ HMMA bf16 split-GEMM, cp.async double-buffered, occ 2 ================
#define GT_STRIDE 80
#define GT_TILE   (128*GT_STRIDE)       // 10240
#define G_AH 0
#define G_AL GT_TILE
#define G_BH (2*GT_TILE)
#define G_BL (3*GT_TILE)
#define GBUF  (4*GT_TILE)               // 40960 per buffer
#define GSMEM (2*GBUF)                  // 81920

__global__ __launch_bounds__(256, 2)
void gemm_tc16(const __nv_bfloat16* __restrict__ Ah, const __nv_bfloat16* __restrict__ Al,
               const __nv_bfloat16* __restrict__ Bh, const __nv_bfloat16* __restrict__ Bl,
               const float* __restrict__ bias, float* __restrict__ C,
               int N, int K)
{
    extern __shared__ __align__(16) char smem[];
    uint32_t sb = smem_u32(smem);

    int tid = threadIdx.x;
    int wid = tid >> 5, lane = tid & 31;
    int wm = wid >> 1, wn = wid & 1;
    int gid = lane >> 2, tig = lane & 3;
    int m0 = blockIdx.y * 128, n0 = blockIdx.x * 128;

    float acc[2][8][4];
    #pragma unroll
    for (int i = 0; i < 2; i++)
        #pragma unroll
        for (int j = 0; j < 8; j++)
            #pragma unroll
            for (int c = 0; c < 4; c++) acc[i][j][c] = 0.f;

    int lrow = tid >> 2, lseg = tid & 3;

    auto issue = [&](int kc0, uint32_t bufo) {
        #pragma unroll
        for (int i = 0; i < 2; i++) {
            int row = lrow + i * 64;
            size_t ga = (size_t)(m0 + row) * K + kc0 + lseg * 8;
            size_t gb = (size_t)(n0 + row) * K + kc0 + lseg * 8;
            uint32_t so = sb + bufo + (uint32_t)(row * GT_STRIDE + lseg * 16);
            CP_ASYNC16(so + G_AH, Ah + ga);
            CP_ASYNC16(so + G_AL, Al + ga);
            CP_ASYNC16(so + G_BH, Bh + gb);
            CP_ASYNC16(so + G_BL, Bl + gb);
        }
    };

    int sub = lane >> 3, rin = lane & 7;
    uint32_t aoff = (uint32_t)((wm*32 + (sub & 1)*8 + rin) * GT_STRIDE + (sub >> 1) * 16);
    uint32_t boff = (uint32_t)((wn*64 + (sub >> 1)*8 + rin) * GT_STRIDE + (sub & 1) * 16);

    int nch = K >> 5;
    issue(0, 0); CP_COMMIT();
    issue(32, GBUF); CP_COMMIT();

    for (int ch = 0; ch < nch; ch++) {
        uint32_t bufo = (uint32_t)(ch & 1) * GBUF;
        CP_WAIT1();
        __syncthreads();

        #pragma unroll
        for (int ks = 0; ks < 2; ks++) {
            // A fragments (hi+lo) for this ks
            uint32_t fAh[2][4], fAl[2][4];
            #pragma unroll
            for (int am = 0; am < 2; am++) {
                uint32_t ad = sb + bufo + aoff + am * (16 * GT_STRIDE) + ks * 32;
                LDSM_X4(fAh[am][0], fAh[am][1], fAh[am][2], fAh[am][3], ad + G_AH);
                LDSM_X4(fAl[am][0], fAl[am][1], fAl[am][2], fAl[am][3], ad + G_AL);
            }
            // B in 4 groups of 2 n-tiles, consumed immediately (low reg pressure)
            #pragma unroll
            for (int bg = 0; bg < 4; bg++) {
                uint32_t bd = sb + bufo + boff + bg * (16 * GT_STRIDE) + ks * 32;
                uint32_t bh0[2], bh1[2], bl0[2], bl1[2];
                LDSM_X4(bh0[0], bh0[1], bh1[0], bh1[1], bd + G_BH);
                LDSM_X4(bl0[0], bl0[1], bl1[0], bl1[1], bd + G_BL);
                #pragma unroll
                for (int am = 0; am < 2; am++) {
                    MMA_BF16(acc[am][2*bg],   fAh[am], bh0);
                    MMA_BF16(acc[am][2*bg],   fAh[am], bl0);
                    MMA_BF16(acc[am][2*bg],   fAl[am], bh0);
                    MMA_BF16(acc[am][2*bg+1], fAh[am], bh1);
                    MMA_BF16(acc[am][2*bg+1], fAh[am], bl1);
                    MMA_BF16(acc[am][2*bg+1], fAl[am], bh1);
                }
            }
        }
        __syncthreads();
        if (ch + 2 < nch) issue((ch + 2) << 5, bufo);
        CP_COMMIT();
    }

    #pragma unroll
    for (int am = 0; am < 2; am++) {
        int row = m0 + wm*32 + am*16 + gid;
        #pragma unroll
        for (int nb = 0; nb < 8; nb++) {
            int col = n0 + wn*64 + nb*8 + tig*2;
            float2 bv = *(const float2*)(bias + col);
            float2 o0 = { acc[am][nb][0] + bv.x, acc[am][nb][1] + bv.y };
            float2 o1 = { acc[am][nb][2] + bv.x, acc[am][nb][3] + bv.y };
            *(float2*)(C + (size_t)row * N + col)       = o0;
            *(float2*)(C + (size_t)(row + 8) * N + col) = o1;
        }
    }
}

// ---------------- mask dtype detection ----------------
__global__ void detect_mask_kind(const void* mask)
{
    __shared__ int s_int, s_float;
    if (threadIdx.x == 0) { s_int = 1; s_float = 1; }
    __syncthreads();
    const unsigned int* w = (const unsigned int*)mask;
    int ok_i = 1, ok_f = 1;
    for (int i = threadIdx.x; i < 1024; i += blockDim.x) {
        unsigned int v = w[i];
        if (v > 1u) ok_i = 0;
        if (v != 0u && v != 0x3F800000u) ok_f = 0;
    }
    atomicAnd(&s_int, ok_i);
    atomicAnd(&s_float, ok_f);
    __syncthreads();
    if (threadIdx.x == 0) g_mask_kind = s_int ? 0 : (s_float ? 1 : 2);
}

// ---------------- pair [B,T,T,H] -> biasT [B,H,T,T], folding mask ----------------
__global__ void bias_transpose_kernel(const float* __restrict__ pair,
                                      const void* __restrict__ mask)
{
    __shared__ float sp[128][9];
    __shared__ float addm[128];
    int b = blockIdx.z, i = blockIdx.y, j0 = blockIdx.x * 128;
    int t = threadIdx.x;

    const float* src = pair + (((size_t)(b * TT + i) * TT) + j0) * HH;
    {
        int f = t * 4;
        int tj = f >> 3;
        int h0 = f & 7;
        float4 v = *(const float4*)(src + f);
        sp[tj][h0]   = v.x; sp[tj][h0+1] = v.y;
        sp[tj][h0+2] = v.z; sp[tj][h0+3] = v.w;
    }
    if (t < 128) {
        size_t mi = ((size_t)(b * TT + i)) * TT + j0 + t;
        int kind = g_mask_kind;
        bool mv;
        if (kind == 0)      mv = ((const int*)mask)[mi] != 0;
        else if (kind == 1) mv = ((const float*)mask)[mi] != 0.f;
        else                mv = ((const unsigned char*)mask)[mi] != 0;
        addm[t] = mv ? 0.f : NEGF;
    }
    __syncthreads();
    #pragma unroll
    for (int u = 0; u < 4; u++) {
        int f = t + 256 * u;
        int h = f >> 7;
        int tj = f & 127;
        g_biasT[(((size_t)(b * HH + h) * TT + i) * TT) + j0 + tj] = sp[tj][h] + addm[tj];
    }
}

// ================ HMMA flash attention, cp.async double-buffered ================
#define FT_STRIDE 144
#define FS_KH 0
#define FS_KL 9216
#define FS_VH 18432
#define FS_VL 27648
#define FS_BIAS 36864
#define FB_STRIDE 272
#define FBUF (36864 + 64*FB_STRIDE)     // 54272 per buffer
#define FSM_TOT (2*FBUF)                // 108544

__global__ __launch_bounds__(128, 2)
void flash_hmma(const __nv_bfloat16* __restrict__ qh, const __nv_bfloat16* __restrict__ ql,
                const __nv_bfloat16* __restrict__ kh, const __nv_bfloat16* __restrict__ kl,
                const __nv_bfloat16* __restrict__ vh, const __nv_bfloat16* __restrict__ vl,
                __nv_bfloat16* __restrict__ oh, __nv_bfloat16* __restrict__ ol)
{
    extern __shared__ __align__(16) char sm[];
    uint32_t sb = smem_u32(sm);
    int tid = threadIdx.x;
    int w = tid >> 5, lane = tid & 31;
    int gid = lane >> 2, tig = lane & 3;
    int sub = lane >> 3, rin = lane & 7;
    int bh = blockIdx.y;
    int b = bh >> 3, h = bh & 7;
    int i0 = blockIdx.x * 64;

    // ---- stage Q tile (hi/lo) into buf0 KH/KL slots, extract A-fragments ----
    const __nv_bfloat16* qhp = qh + ((size_t)(b*TT + i0)) * CC + h * DD;
    const __nv_bfloat16* qlp = ql + ((size_t)(b*TT + i0)) * CC + h * DD;
    #pragma unroll
    for (int u = 0; u < 4; u++) {
        int f = u * 128 + tid;
        int row = f >> 3, seg = f & 7;
        *(float4*)(sm + FS_KH + row*FT_STRIDE + seg*16) = *(const float4*)(qhp + (size_t)row*CC + seg*8);
        *(float4*)(sm + FS_KL + row*FT_STRIDE + seg*16) = *(const float4*)(qlp + (size_t)row*CC + seg*8);
    }
    __syncthreads();
    uint32_t qfh[4][4], qfl[4][4];
    {
        uint32_t qa = sb + (uint32_t)((w*16 + (sub & 1)*8 + rin) * FT_STRIDE + (sub >> 1)*16);
        #pragma unroll
        for (int kb = 0; kb < 4; kb++) {
            LDSM_X4(qfh[kb][0], qfh[kb][1], qfh[kb][2], qfh[kb][3], qa + FS_KH + kb*32);
            LDSM_X4(qfl[kb][0], qfl[kb][1], qfl[kb][2], qfl[kb][3], qa + FS_KL + kb*32);
        }
    }
    __syncthreads();

    float accO[8][4];
    #pragma unroll
    for (int nb = 0; nb < 8; nb++)
        #pragma unroll
        for (int c = 0; c < 4; c++) accO[nb][c] = 0.f;
    float mrow0 = -3.0e38f, mrow1 = -3.0e38f;
    float lrow0 = 0.f, lrow1 = 0.f;

    const __nv_bfloat16* khp = kh + ((size_t)(b*TT)) * CC + h * DD;
    const __nv_bfloat16* klp = kl + ((size_t)(b*TT)) * CC + h * DD;
    const __nv_bfloat16* vhp = vh + ((size_t)(b*TT)) * CC + h * DD;
    const __nv_bfloat16* vlp = vl + ((size_t)(b*TT)) * CC + h * DD;
    const float* bbase = g_biasT + ((size_t)bh * TT + i0) * TT;

    auto issue_tile = [&](int jt, uint32_t bufo) {
        int j0 = jt * 64;
        #pragma unroll
        for (int u = 0; u < 4; u++) {
            int f = u * 128 + tid;
            int row = f >> 3, seg = f & 7;
            size_t g = (size_t)(j0 + row) * CC + seg * 8;
            uint32_t so = sb + bufo + (uint32_t)(row*FT_STRIDE + seg*16);
            CP_ASYNC16(so + FS_KH, khp + g);
            CP_ASYNC16(so + FS_KL, klp + g);
            CP_ASYNC16(so + FS_VH, vhp + g);
            CP_ASYNC16(so + FS_VL, vlp + g);
        }
        #pragma unroll
        for (int u = 0; u < 8; u++) {
            int f = u * 128 + tid;
            int row = f >> 4, seg = f & 15;
            CP_ASYNC16(sb + bufo + FS_BIAS + (uint32_t)(row*FB_STRIDE + seg*16),
                       bbase + (size_t)row*TT + j0 + seg*4);
        }
    };

    uint32_t kfo = (uint32_t)(((sub >> 1)*8 + rin) * FT_STRIDE + (sub & 1)*16);
    uint32_t vfo = (uint32_t)(((sub & 1)*8 + rin) * FT_STRIDE + (sub >> 1)*16);

    issue_tile(0, 0); CP_COMMIT();
    issue_tile(1, FBUF); CP_COMMIT();

    for (int jt = 0; jt < 16; jt++) {
        uint32_t bufo = (uint32_t)(jt & 1) * FBUF;
        CP_WAIT1();
        __syncthreads();

        // ---- S = Q K^T + bias ----
        float s[8][4];
        #pragma unroll
        for (int nb = 0; nb < 8; nb++) {
            int brow = w*16 + gid;
            int bcol = (nb*8 + tig*2) * 4;
            float2 b0 = *(const float2*)(sm + bufo + FS_BIAS + brow*FB_STRIDE + bcol);
            float2 b1 = *(const float2*)(sm + bufo + FS_BIAS + (brow+8)*FB_STRIDE + bcol);
            s[nb][0] = b0.x; s[nb][1] = b0.y; s[nb][2] = b1.x; s[nb][3] = b1.y;
        }
        #pragma unroll
        for (int kb = 0; kb < 4; kb++) {
            #pragma unroll
            for (int nb2 = 0; nb2 < 4; nb2++) {
                uint32_t ka = sb + bufo + kfo + (uint32_t)(nb2*16*FT_STRIDE + kb*32);
                uint32_t kh0[2], kh1[2], kl0[2], kl1[2];
                LDSM_X4(kh0[0], kh0[1], kh1[0], kh1[1], ka + FS_KH);
                LDSM_X4(kl0[0], kl0[1], kl1[0], kl1[1], ka + FS_KL);
                MMA_BF16(s[2*nb2],   qfh[kb], kh0);
                MMA_BF16(s[2*nb2],   qfh[kb], kl0);
                MMA_BF16(s[2*nb2],   qfl[kb], kh0);
                MMA_BF16(s[2*nb2+1], qfh[kb], kh1);
                MMA_BF16(s[2*nb2+1], qfh[kb], kl1);
                MMA_BF16(s[2*nb2+1], qfl[kb], kh1);
            }
        }

        // ---- online softmax ----
        float mt0 = s[0][0], mt1 = s[0][2];
        #pragma unroll
        for (int nb = 0; nb < 8; nb++) {
            mt0 = fmaxf(mt0, fmaxf(s[nb][0], s[nb][1]));
            mt1 = fmaxf(mt1, fmaxf(s[nb][2], s[nb][3]));
        }
        mt0 = fmaxf(mt0, __shfl_xor_sync(0xffffffffu, mt0, 1));
        mt0 = fmaxf(mt0, __shfl_xor_sync(0xffffffffu, mt0, 2));
        mt1 = fmaxf(mt1, __shfl_xor_sync(0xffffffffu, mt1, 1));
        mt1 = fmaxf(mt1, __shfl_xor_sync(0xffffffffu, mt1, 2));
        float mn0 = fmaxf(mrow0, mt0), mn1 = fmaxf(mrow1, mt1);
        float c0 = fexp(mrow0 - mn0), c1 = fexp(mrow1 - mn1);
        lrow0 *= c0; lrow1 *= c1;
        #pragma unroll
        for (int nb = 0; nb < 8; nb++) {
            accO[nb][0] *= c0; accO[nb][1] *= c0;
            accO[nb][2] *= c1; accO[nb][3] *= c1;
        }
        #pragma unroll
        for (int nb = 0; nb < 8; nb++) {
            s[nb][0] = fexp(s[nb][0] - mn0);
            s[nb][1] = fexp(s[nb][1] - mn0);
            s[nb][2] = fexp(s[nb][2] - mn1);
            s[nb][3] = fexp(s[nb][3] - mn1);
            lrow0 += s[nb][0] + s[nb][1];
            lrow1 += s[nb][2] + s[nb][3];
        }
        mrow0 = mn0; mrow1 = mn1;

        // ---- O += P V ----
        #pragma unroll
        for (int kb = 0; kb < 4; kb++) {
            uint32_t ph[4], pl[4];
            {
                int ne = 2*kb, no = 2*kb + 1;
                __nv_bfloat162 H;
                H = __floats2bfloat162_rn(s[ne][0], s[ne][1]);
                ph[0] = *reinterpret_cast<uint32_t*>(&H);
                pl[0] = pack_bf16x2(s[ne][0] - __low2float(H), s[ne][1] - __high2float(H));
                H = __floats2bfloat162_rn(s[ne][2], s[ne][3]);
                ph[1] = *reinterpret_cast<uint32_t*>(&H);
                pl[1] = pack_bf16x2(s[ne][2] - __low2float(H), s[ne][3] - __high2float(H));
                H = __floats2bfloat162_rn(s[no][0], s[no][1]);
                ph[2] = *reinterpret_cast<uint32_t*>(&H);
                pl[2] = pack_bf16x2(s[no][0] - __low2float(H), s[no][1] - __high2float(H));
                H = __floats2bfloat162_rn(s[no][2], s[no][3]);
                ph[3] = *reinterpret_cast<uint32_t*>(&H);
                pl[3] = pack_bf16x2(s[no][2] - __low2float(H), s[no][3] - __high2float(H));
            }
            #pragma unroll
            for (int db2 = 0; db2 < 4; db2++) {
                uint32_t va = sb + bufo + vfo + (uint32_t)(kb*16*FT_STRIDE + db2*32);
                uint32_t vhe[2], vho[2], vle[2], vlo[2];
                LDSM_X4_T(vhe[0], vhe[1], vho[0], vho[1], va + FS_VH);
                LDSM_X4_T(vle[0], vle[1], vlo[0], vlo[1], va + FS_VL);
                MMA_BF16(accO[2*db2],   ph, vhe);
                MMA_BF16(accO[2*db2],   ph, vle);
                MMA_BF16(accO[2*db2],   pl, vhe);
                MMA_BF16(accO[2*db2+1], ph, vho);
                MMA_BF16(accO[2*db2+1], ph, vlo);
                MMA_BF16(accO[2*db2+1], pl, vho);
            }
        }

        __syncthreads();
        if (jt + 2 < 16) issue_tile(jt + 2, bufo);
        CP_COMMIT();
    }

    // ---- finalize ----
    lrow0 += __shfl_xor_sync(0xffffffffu, lrow0, 1);
    lrow0 += __shfl_xor_sync(0xffffffffu, lrow0, 2);
    lrow1 += __shfl_xor_sync(0xffffffffu, lrow1, 1);
    lrow1 += __shfl_xor_sync(0xffffffffu, lrow1, 2);
    float inv0 = 1.f / lrow0, inv1 = 1.f / lrow1;

    size_t r0 = (size_t)(b*TT + i0 + w*16 + gid) * CC + h * DD;
    size_t r1 = r0 + 8 * CC;
    #pragma unroll
    for (int nb = 0; nb < 8; nb++) {
        int col = nb*8 + tig*2;
        float o00 = accO[nb][0]*inv0, o01 = accO[nb][1]*inv0;
        float o10 = accO[nb][2]*inv1, o11 = accO[nb][3]*inv1;
        __nv_bfloat162 H0 = __floats2bfloat162_rn(o00, o01);
        __nv_bfloat162 H1 = __floats2bfloat162_rn(o10, o11);
        *(__nv_bfloat162*)(oh + r0 + col) = H0;
        *(__nv_bfloat162*)(oh + r1 + col) = H1;
        *(__nv_bfloat162*)(ol + r0 + col) =
            __floats2bfloat162_rn(o00 - __low2float(H0), o01 - __high2float(H0));
        *(__nv_bfloat162*)(ol + r1 + col) =
            __floats2bfloat162_rn(o10 - __low2float(H1), o11 - __high2float(H1));
    }
}

// ---------------- launch ----------------
extern "C" void kernel_launch(void* const* d_in, const int* in_sizes, int n_in,
                              void* d_out, int out_size)
{
    const float* x      = (const float*)d_in[0];
    const float* pair   = (const float*)d_in[1];
    const void*  mask   = d_in[2];
    const float* norm_w = (const float*)d_in[3];
    const float* norm_b = (const float*)d_in[4];
    const float* qkv_w  = (const float*)d_in[5];
    const float* qkv_b  = (const float*)d_in[6];
    const float* qln_w  = (const float*)d_in[7];
    const float* qln_b  = (const float*)d_in[8];
    const float* kln_w  = (const float*)d_in[9];
    const float* kln_b  = (const float*)d_in[10];
    const float* proj_w = (const float*)d_in[11];
    const float* proj_b = (const float*)d_in[12];
    float* out = (float*)d_out;

    float *qkvp;
    __nv_bfloat16 *ah, *al, *wh, *wl, *qh, *ql, *kh, *kl, *vh, *vl;
    cudaGetSymbolAddress((void**)&qkvp, g_qkv);
    cudaGetSymbolAddress((void**)&ah, g_ah);
    cudaGetSymbolAddress((void**)&al, g_al);
    cudaGetSymbolAddress((void**)&wh, g_wh);
    cudaGetSymbolAddress((void**)&wl, g_wl);
    cudaGetSymbolAddress((void**)&qh, g_qh);
    cudaGetSymbolAddress((void**)&ql, g_ql);
    cudaGetSymbolAddress((void**)&kh, g_kh);
    cudaGetSymbolAddress((void**)&kl, g_kl);
    cudaGetSymbolAddress((void**)&vh, g_vh);
    cudaGetSymbolAddress((void**)&vl, g_vl);

    cudaFuncSetAttribute(flash_hmma, cudaFuncAttributeMaxDynamicSharedMemorySize, FSM_TOT);
    cudaFuncSetAttribute(gemm_tc16, cudaFuncAttributeMaxDynamicSharedMemorySize, GSMEM);

    // 0. mask dtype detection (front of stream)
    detect_mask_kind<<<1, 256>>>(mask);
    // 1. pre-norm + bf16 split
    ln_split_kernel<<<NROWS, 128>>>(x, norm_w, norm_b, ah, al);
    // 2. split qkv weights + QKV GEMM (HMMA)
    split_kernel<<<(C3*CC/4 + 255)/256, 256>>>(qkv_w, wh, wl, C3*CC/4);
    gemm_tc16<<<dim3(C3/128, NROWS/128), 256, GSMEM>>>(ah, al, wh, wl, qkv_b, qkvp, C3, CC);
    // 3. q/k LN + scale fold + bf16 splits (fused)
    qkv_post<<<NROWS, 128>>>(qkvp, qln_w, qln_b, kln_w, kln_b);
    // 4. pair transpose with mask fold
    bias_transpose_kernel<<<dim3(TT/128, TT, BB), 256>>>(pair, mask);
    // 5. HMMA flash attention -> bf16 hi/lo directly
    flash_hmma<<<dim3(TT/64, BB*HH), 128, FSM_TOT>>>(qh, ql, kh, kl, vh, vl, ah, al);
    // 6. output projection (HMMA)
    split_kernel<<<(CC*CC/4 + 255)/256, 256>>>(proj_w, wh, wl, CC*CC/4);
    gemm_tc16<<<dim3(CC/128, NROWS/128), 256, GSMEM>>>(ah, al, wh, wl, proj_b, out, CC, CC);
}

// round 7
// speedup vs baseline: 1.0249x; 1.0249x over previous
#include <cuda_runtime.h>
#include <cuda_bf16.h>
#include <cstdint>

// Problem constants
#define BB 4
#define TT 1024
#define CC 512
#define HH 8
#define DD 64
#define NROWS (BB*TT)          // 4096
#define C3 (3*CC)              // 1536
#define NEGF (-3.402823466e38f)

// -------- scratch (static device globals; allocation-free) --------
__device__ float g_qkv[(size_t)NROWS*C3];         // 24 MB
__device__ float g_biasT[(size_t)BB*HH*TT*TT];    // 128 MB
__device__ int   g_mask_kind;
__device__ __nv_bfloat16 g_ah[(size_t)NROWS*CC];  // A hi (also attn out hi)
__device__ __nv_bfloat16 g_al[(size_t)NROWS*CC];  // A lo
__device__ __nv_bfloat16 g_wh[(size_t)C3*CC];
__device__ __nv_bfloat16 g_wl[(size_t)C3*CC];
__device__ __nv_bfloat16 g_qh[(size_t)NROWS*CC];
__device__ __nv_bfloat16 g_ql[(size_t)NROWS*CC];
__device__ __nv_bfloat16 g_kh[(size_t)NROWS*CC];
__device__ __nv_bfloat16 g_kl[(size_t)NROWS*CC];
__device__ __nv_bfloat16 g_vh[(size_t)NROWS*CC];
__device__ __nv_bfloat16 g_vl[(size_t)NROWS*CC];

// ================ generic-PTX helpers ================
__device__ __forceinline__ uint32_t smem_u32(const void* p) {
    uint32_t a;
    asm("{ .reg .u64 t; cvta.to.shared.u64 t, %1; cvt.u32.u64 %0, t; }"
        : "=r"(a) : "l"(p));
    return a;
}
#define LDSM_X4(r0, r1, r2, r3, addr) \
    asm volatile("ldmatrix.sync.aligned.m8n8.x4.shared.b16 {%0,%1,%2,%3}, [%4];" \
        : "=r"(r0), "=r"(r1), "=r"(r2), "=r"(r3) : "r"(addr))
#define LDSM_X4_T(r0, r1, r2, r3, addr) \
    asm volatile("ldmatrix.sync.aligned.m8n8.x4.trans.shared.b16 {%0,%1,%2,%3}, [%4];" \
        : "=r"(r0), "=r"(r1), "=r"(r2), "=r"(r3) : "r"(addr))
#define MMA_BF16(d, a, b) \
    asm volatile("mma.sync.aligned.m16n8k16.row.col.f32.bf16.bf16.f32 " \
        "{%0,%1,%2,%3}, {%4,%5,%6,%7}, {%8,%9}, {%0,%1,%2,%3};" \
        : "+f"((d)[0]), "+f"((d)[1]), "+f"((d)[2]), "+f"((d)[3]) \
        : "r"((a)[0]), "r"((a)[1]), "r"((a)[2]), "r"((a)[3]), \
          "r"((b)[0]), "r"((b)[1]))
#define CP_ASYNC16(saddr, gptr) \
    asm volatile("cp.async.cg.shared.global [%0], [%1], 16;" \
        :: "r"(saddr), "l"(gptr))
#define CP_COMMIT() asm volatile("cp.async.commit_group;" ::: "memory")
#define CP_WAIT1()  asm volatile("cp.async.wait_group 1;" ::: "memory")

__device__ __forceinline__ uint32_t pack_bf16x2(float a, float b) {
    __nv_bfloat162 t = __floats2bfloat162_rn(a, b);
    return *reinterpret_cast<uint32_t*>(&t);
}

// fast exp on FMA pipe
__device__ __forceinline__ float fexp(float x) {
    float t = fmaxf(x * 1.4426950408889634f, -126.f);
    float fi = floorf(t);
    float f = t - fi;
    float p = 1.5403530393381609e-4f;
    p = fmaf(p, f, 1.3333558146428443e-3f);
    p = fmaf(p, f, 9.6181291976036826e-3f);
    p = fmaf(p, f, 5.5504108664821580e-2f);
    p = fmaf(p, f, 2.4022650695910071e-1f);
    p = fmaf(p, f, 6.9314718055994531e-1f);
    p = fmaf(p, f, 1.0f);
    int ii = (int)fi;
    return p * __int_as_float((ii + 127) << 23);
}

// ================ LayerNorm core ================
__device__ __forceinline__ float warp_sum(float v) {
    #pragma unroll
    for (int o = 16; o; o >>= 1) v += __shfl_xor_sync(0xffffffffu, v, o);
    return v;
}

__device__ __forceinline__ void ln_core(float4& v, const float* w, const float* b,
                                        int t, float4& o)
{
    float s  = v.x + v.y + v.z + v.w;
    float sq = v.x*v.x + v.y*v.y + v.z*v.z + v.w*v.w;
    s = warp_sum(s); sq = warp_sum(sq);
    __shared__ float sh[8];
    int wid = t >> 5, lid = t & 31;
    if (lid == 0) { sh[wid] = s; sh[4 + wid] = sq; }
    __syncthreads();
    float ts = sh[0] + sh[1] + sh[2] + sh[3];
    float tq = sh[4] + sh[5] + sh[6] + sh[7];
    float mean = ts * (1.f / CC);
    float var  = tq * (1.f / CC) - mean * mean;
    float rstd = rsqrtf(var + 1e-5f);
    float4 wv = *(const float4*)(w + t * 4);
    float4 bv = *(const float4*)(b + t * 4);
    o.x = (v.x - mean) * rstd * wv.x + bv.x;
    o.y = (v.y - mean) * rstd * wv.y + bv.y;
    o.z = (v.z - mean) * rstd * wv.z + bv.z;
    o.w = (v.w - mean) * rstd * wv.w + bv.w;
}

__device__ __forceinline__ void split_store4(float4 o, __nv_bfloat16* hi,
                                             __nv_bfloat16* lo, size_t base)
{
    float vv[4] = {o.x, o.y, o.z, o.w};
    __nv_bfloat16 h[4]; float r[4];
    #pragma unroll
    for (int u = 0; u < 4; u++) { h[u] = __float2bfloat16(vv[u]); r[u] = vv[u] - __bfloat162float(h[u]); }
    *(__nv_bfloat162*)(hi + base)     = __nv_bfloat162{h[0], h[1]};
    *(__nv_bfloat162*)(hi + base + 2) = __nv_bfloat162{h[2], h[3]};
    *(__nv_bfloat162*)(lo + base)     = __floats2bfloat162_rn(r[0], r[1]);
    *(__nv_bfloat162*)(lo + base + 2) = __floats2bfloat162_rn(r[2], r[3]);
}

__global__ void ln_split_kernel(const float* src, const float* __restrict__ w,
                                const float* __restrict__ b,
                                __nv_bfloat16* hi, __nv_bfloat16* lo)
{
    int row = blockIdx.x, t = threadIdx.x;
    float4 v = *(const float4*)(src + (size_t)row * CC + t * 4);
    float4 o;
    ln_core(v, w, b, t, o);
    split_store4(o, hi, lo, (size_t)row * CC + t * 4);
}

__global__ void qkv_post(const float* __restrict__ qkv,
                         const float* __restrict__ qw, const float* __restrict__ qb,
                         const float* __restrict__ kw, const float* __restrict__ kb)
{
    int row = blockIdx.x, t = threadIdx.x;
    const float* rp = qkv + (size_t)row * C3;
    size_t base = (size_t)row * CC + t * 4;
    float4 v = *(const float4*)(rp + t * 4);
    float4 o;
    ln_core(v, qw, qb, t, o);
    o.x *= 0.125f; o.y *= 0.125f; o.z *= 0.125f; o.w *= 0.125f;
    split_store4(o, g_qh, g_ql, base);
    __syncthreads();
    v = *(const float4*)(rp + CC + t * 4);
    ln_core(v, kw, kb, t, o);
    split_store4(o, g_kh, g_kl, base);
    v = *(const float4*)(rp + 2 * CC + t * 4);
    split_store4(v, g_vh, g_vl, base);
}

__global__ void split_kernel(const float* __restrict__ src,
                             __nv_bfloat16* hi, __nv_bfloat16* lo, int n4)
{
    int i = blockIdx.x * blockDim.x + threadIdx.x;
    if (i >= n4) return;
    float4 v = ((const float4*)src)[i];
    split_store4(v, hi, lo, (size_t)i * 4);
}

// ================ HMMA bf16 split-GEMM, cp.async double-buffered, occ 2 ================
// MMA schedule is product-major so consecutive volatile MMAs never share an
// accumulator (reuse distance 8 >= HMMA latency / rt).
#define GT_STRIDE 80
#define GT_TILE   (128*GT_STRIDE)       // 10240
#define G_AH 0
#define G_AL GT_TILE
#define G_BH (2*GT_TILE)
#define G_BL (3*GT_TILE)
#define GBUF  (4*GT_TILE)               // 40960 per buffer
#define GSMEM (2*GBUF)                  // 81920

__global__ __launch_bounds__(256, 2)
void gemm_tc16(const __nv_bfloat16* __restrict__ Ah, const __nv_bfloat16* __restrict__ Al,
               const __nv_bfloat16* __restrict__ Bh, const __nv_bfloat16* __restrict__ Bl,
               const float* __restrict__ bias, float* __restrict__ C,
               int N, int K)
{
    extern __shared__ __align__(16) char smem[];
    uint32_t sb = smem_u32(smem);

    int tid = threadIdx.x;
    int wid = tid >> 5, lane = tid & 31;
    int wm = wid >> 1, wn = wid & 1;
    int gid = lane >> 2, tig = lane & 3;
    int m0 = blockIdx.y * 128, n0 = blockIdx.x * 128;

    float acc[2][8][4];
    #pragma unroll
    for (int i = 0; i < 2; i++)
        #pragma unroll
        for (int j = 0; j < 8; j++)
            #pragma unroll
            for (int c = 0; c < 4; c++) acc[i][j][c] = 0.f;

    int lrow = tid >> 2, lseg = tid & 3;

    auto issue = [&](int kc0, uint32_t bufo) {
        #pragma unroll
        for (int i = 0; i < 2; i++) {
            int row = lrow + i * 64;
            size_t ga = (size_t)(m0 + row) * K + kc0 + lseg * 8;
            size_t gb = (size_t)(n0 + row) * K + kc0 + lseg * 8;
            uint32_t so = sb + bufo + (uint32_t)(row * GT_STRIDE + lseg * 16);
            CP_ASYNC16(so + G_AH, Ah + ga);
            CP_ASYNC16(so + G_AL, Al + ga);
            CP_ASYNC16(so + G_BH, Bh + gb);
            CP_ASYNC16(so + G_BL, Bl + gb);
        }
    };

    int sub = lane >> 3, rin = lane & 7;
    uint32_t aoff = (uint32_t)((wm*32 + (sub & 1)*8 + rin) * GT_STRIDE + (sub >> 1) * 16);
    uint32_t boff = (uint32_t)((wn*64 + (sub >> 1)*8 + rin) * GT_STRIDE + (sub & 1) * 16);

    int nch = K >> 5;
    issue(0, 0); CP_COMMIT();
    issue(32, GBUF); CP_COMMIT();

    for (int ch = 0; ch < nch; ch++) {
        uint32_t bufo = (uint32_t)(ch & 1) * GBUF;
        CP_WAIT1();
        __syncthreads();

        #pragma unroll
        for (int ks = 0; ks < 2; ks++) {
            // A fragments (hi+lo) for this ks
            uint32_t fAh[2][4], fAl[2][4];
            #pragma unroll
            for (int am = 0; am < 2; am++) {
                uint32_t ad = sb + bufo + aoff + am * (16 * GT_STRIDE) + ks * 32;
                LDSM_X4(fAh[am][0], fAh[am][1], fAh[am][2], fAh[am][3], ad + G_AH);
                LDSM_X4(fAl[am][0], fAl[am][1], fAl[am][2], fAl[am][3], ad + G_AL);
            }
            // B in halves of 4 n-tiles; product-major MMA schedule inside
            #pragma unroll
            for (int half = 0; half < 2; half++) {
                uint32_t bh[4][2], bl[4][2];
                #pragma unroll
                for (int bg = 0; bg < 2; bg++) {
                    uint32_t bd = sb + bufo + boff
                                + (half * 2 + bg) * (16 * GT_STRIDE) + ks * 32;
                    LDSM_X4(bh[2*bg][0], bh[2*bg][1], bh[2*bg+1][0], bh[2*bg+1][1], bd + G_BH);
                    LDSM_X4(bl[2*bg][0], bl[2*bg][1], bl[2*bg+1][0], bl[2*bg+1][1], bd + G_BL);
                }
                // pass 1: Ah * Bh  (8 independent accumulators)
                #pragma unroll
                for (int am = 0; am < 2; am++)
                    #pragma unroll
                    for (int nb = 0; nb < 4; nb++)
                        MMA_BF16(acc[am][half*4+nb], fAh[am], bh[nb]);
                // pass 2: Ah * Bl
                #pragma unroll
                for (int am = 0; am < 2; am++)
                    #pragma unroll
                    for (int nb = 0; nb < 4; nb++)
                        MMA_BF16(acc[am][half*4+nb], fAh[am], bl[nb]);
                // pass 3: Al * Bh
                #pragma unroll
                for (int am = 0; am < 2; am++)
                    #pragma unroll
                    for (int nb = 0; nb < 4; nb++)
                        MMA_BF16(acc[am][half*4+nb], fAl[am], bh[nb]);
            }
        }
        __syncthreads();
        if (ch + 2 < nch) issue((ch + 2) << 5, bufo);
        CP_COMMIT();
    }

    #pragma unroll
    for (int am = 0; am < 2; am++) {
        int row = m0 + wm*32 + am*16 + gid;
        #pragma unroll
        for (int nb = 0; nb < 8; nb++) {
            int col = n0 + wn*64 + nb*8 + tig*2;
            float2 bv = *(const float2*)(bias + col);
            float2 o0 = { acc[am][nb][0] + bv.x, acc[am][nb][1] + bv.y };
            float2 o1 = { acc[am][nb][2] + bv.x, acc[am][nb][3] + bv.y };
            *(float2*)(C + (size_t)row * N + col)       = o0;
            *(float2*)(C + (size_t)(row + 8) * N + col) = o1;
        }
    }
}

// ---------------- mask dtype detection ----------------
__global__ void detect_mask_kind(const void* mask)
{
    __shared__ int s_int, s_float;
    if (threadIdx.x == 0) { s_int = 1; s_float = 1; }
    __syncthreads();
    const unsigned int* w = (const unsigned int*)mask;
    int ok_i = 1, ok_f = 1;
    for (int i = threadIdx.x; i < 1024; i += blockDim.x) {
        unsigned int v = w[i];
        if (v > 1u) ok_i = 0;
        if (v != 0u && v != 0x3F800000u) ok_f = 0;
    }
    atomicAnd(&s_int, ok_i);
    atomicAnd(&s_float, ok_f);
    __syncthreads();
    if (threadIdx.x == 0) g_mask_kind = s_int ? 0 : (s_float ? 1 : 2);
}

// ---------------- pair [B,T,T,H] -> biasT [B,H,T,T], folding mask ----------------
__global__ void bias_transpose_kernel(const float* __restrict__ pair,
                                      const void* __restrict__ mask)
{
    __shared__ float sp[128][9];
    __shared__ float addm[128];
    int b = blockIdx.z, i = blockIdx.y, j0 = blockIdx.x * 128;
    int t = threadIdx.x;

    const float* src = pair + (((size_t)(b * TT + i) * TT) + j0) * HH;
    {
        int f = t * 4;
        int tj = f >> 3;
        int h0 = f & 7;
        float4 v = *(const float4*)(src + f);
        sp[tj][h0]   = v.x; sp[tj][h0+1] = v.y;
        sp[tj][h0+2] = v.z; sp[tj][h0+3] = v.w;
    }
    if (t < 128) {
        size_t mi = ((size_t)(b * TT + i)) * TT + j0 + t;
        int kind = g_mask_kind;
        bool mv;
        if (kind == 0)      mv = ((const int*)mask)[mi] != 0;
        else if (kind == 1) mv = ((const float*)mask)[mi] != 0.f;
        else                mv = ((const unsigned char*)mask)[mi] != 0;
        addm[t] = mv ? 0.f : NEGF;
    }
    __syncthreads();
    #pragma unroll
    for (int u = 0; u < 4; u++) {
        int f = t + 256 * u;
        int h = f >> 7;
        int tj = f & 127;
        g_biasT[(((size_t)(b * HH + h) * TT + i) * TT) + j0 + tj] = sp[tj][h] + addm[tj];
    }
}

// ================ HMMA flash attention, cp.async double-buffered ================
#define FT_STRIDE 144
#define FS_KH 0
#define FS_KL 9216
#define FS_VH 18432
#define FS_VL 27648
#define FS_BIAS 36864
#define FB_STRIDE 272
#define FBUF (36864 + 64*FB_STRIDE)     // 54272 per buffer
#define FSM_TOT (2*FBUF)                // 108544

__global__ __launch_bounds__(128, 2)
void flash_hmma(const __nv_bfloat16* __restrict__ qh, const __nv_bfloat16* __restrict__ ql,
                const __nv_bfloat16* __restrict__ kh, const __nv_bfloat16* __restrict__ kl,
                const __nv_bfloat16* __restrict__ vh, const __nv_bfloat16* __restrict__ vl,
                __nv_bfloat16* __restrict__ oh, __nv_bfloat16* __restrict__ ol)
{
    extern __shared__ __align__(16) char sm[];
    uint32_t sb = smem_u32(sm);
    int tid = threadIdx.x;
    int w = tid >> 5, lane = tid & 31;
    int gid = lane >> 2, tig = lane & 3;
    int sub = lane >> 3, rin = lane & 7;
    int bh = blockIdx.y;
    int b = bh >> 3, h = bh & 7;
    int i0 = blockIdx.x * 64;

    // ---- stage Q tile (hi/lo) into buf0 KH/KL slots, extract A-fragments ----
    const __nv_bfloat16* qhp = qh + ((size_t)(b*TT + i0)) * CC + h * DD;
    const __nv_bfloat16* qlp = ql + ((size_t)(b*TT + i0)) * CC + h * DD;
    #pragma unroll
    for (int u = 0; u < 4; u++) {
        int f = u * 128 + tid;
        int row = f >> 3, seg = f & 7;
        *(float4*)(sm + FS_KH + row*FT_STRIDE + seg*16) = *(const float4*)(qhp + (size_t)row*CC + seg*8);
        *(float4*)(sm + FS_KL + row*FT_STRIDE + seg*16) = *(const float4*)(qlp + (size_t)row*CC + seg*8);
    }
    __syncthreads();
    uint32_t qfh[4][4], qfl[4][4];
    {
        uint32_t qa = sb + (uint32_t)((w*16 + (sub & 1)*8 + rin) * FT_STRIDE + (sub >> 1)*16);
        #pragma unroll
        for (int kb = 0; kb < 4; kb++) {
            LDSM_X4(qfh[kb][0], qfh[kb][1], qfh[kb][2], qfh[kb][3], qa + FS_KH + kb*32);
            LDSM_X4(qfl[kb][0], qfl[kb][1], qfl[kb][2], qfl[kb][3], qa + FS_KL + kb*32);
        }
    }
    __syncthreads();

    float accO[8][4];
    #pragma unroll
    for (int nb = 0; nb < 8; nb++)
        #pragma unroll
        for (int c = 0; c < 4; c++) accO[nb][c] = 0.f;
    float mrow0 = -3.0e38f, mrow1 = -3.0e38f;
    float lrow0 = 0.f, lrow1 = 0.f;

    const __nv_bfloat16* khp = kh + ((size_t)(b*TT)) * CC + h * DD;
    const __nv_bfloat16* klp = kl + ((size_t)(b*TT)) * CC + h * DD;
    const __nv_bfloat16* vhp = vh + ((size_t)(b*TT)) * CC + h * DD;
    const __nv_bfloat16* vlp = vl + ((size_t)(b*TT)) * CC + h * DD;
    const float* bbase = g_biasT + ((size_t)bh * TT + i0) * TT;

    auto issue_tile = [&](int jt, uint32_t bufo) {
        int j0 = jt * 64;
        #pragma unroll
        for (int u = 0; u < 4; u++) {
            int f = u * 128 + tid;
            int row = f >> 3, seg = f & 7;
            size_t g = (size_t)(j0 + row) * CC + seg * 8;
            uint32_t so = sb + bufo + (uint32_t)(row*FT_STRIDE + seg*16);
            CP_ASYNC16(so + FS_KH, khp + g);
            CP_ASYNC16(so + FS_KL, klp + g);
            CP_ASYNC16(so + FS_VH, vhp + g);
            CP_ASYNC16(so + FS_VL, vlp + g);
        }
        #pragma unroll
        for (int u = 0; u < 8; u++) {
            int f = u * 128 + tid;
            int row = f >> 4, seg = f & 15;
            CP_ASYNC16(sb + bufo + FS_BIAS + (uint32_t)(row*FB_STRIDE + seg*16),
                       bbase + (size_t)row*TT + j0 + seg*4);
        }
    };

    uint32_t kfo = (uint32_t)(((sub >> 1)*8 + rin) * FT_STRIDE + (sub & 1)*16);
    uint32_t vfo = (uint32_t)(((sub & 1)*8 + rin) * FT_STRIDE + (sub >> 1)*16);

    issue_tile(0, 0); CP_COMMIT();
    issue_tile(1, FBUF); CP_COMMIT();

    for (int jt = 0; jt < 16; jt++) {
        uint32_t bufo = (uint32_t)(jt & 1) * FBUF;
        CP_WAIT1();
        __syncthreads();

        // ---- S = Q K^T + bias ----
        float s[8][4];
        #pragma unroll
        for (int nb = 0; nb < 8; nb++) {
            int brow = w*16 + gid;
            int bcol = (nb*8 + tig*2) * 4;
            float2 b0 = *(const float2*)(sm + bufo + FS_BIAS + brow*FB_STRIDE + bcol);
            float2 b1 = *(const float2*)(sm + bufo + FS_BIAS + (brow+8)*FB_STRIDE + bcol);
            s[nb][0] = b0.x; s[nb][1] = b0.y; s[nb][2] = b1.x; s[nb][3] = b1.y;
        }
        #pragma unroll
        for (int kb = 0; kb < 4; kb++) {
            // load all K fragments for this kb, then product-major passes
            uint32_t kfh[8][2], kfl[8][2];
            #pragma unroll
            for (int nb2 = 0; nb2 < 4; nb2++) {
                uint32_t ka = sb + bufo + kfo + (uint32_t)(nb2*16*FT_STRIDE + kb*32);
                LDSM_X4(kfh[2*nb2][0], kfh[2*nb2][1], kfh[2*nb2+1][0], kfh[2*nb2+1][1], ka + FS_KH);
                LDSM_X4(kfl[2*nb2][0], kfl[2*nb2][1], kfl[2*nb2+1][0], kfl[2*nb2+1][1], ka + FS_KL);
            }
            #pragma unroll
            for (int nb = 0; nb < 8; nb++)
                MMA_BF16(s[nb], qfh[kb], kfh[nb]);
            #pragma unroll
            for (int nb = 0; nb < 8; nb++)
                MMA_BF16(s[nb], qfh[kb], kfl[nb]);
            #pragma unroll
            for (int nb = 0; nb < 8; nb++)
                MMA_BF16(s[nb], qfl[kb], kfh[nb]);
        }

        // ---- online softmax ----
        float mt0 = s[0][0], mt1 = s[0][2];
        #pragma unroll
        for (int nb = 0; nb < 8; nb++) {
            mt0 = fmaxf(mt0, fmaxf(s[nb][0], s[nb][1]));
            mt1 = fmaxf(mt1, fmaxf(s[nb][2], s[nb][3]));
        }
        mt0 = fmaxf(mt0, __shfl_xor_sync(0xffffffffu, mt0, 1));
        mt0 = fmaxf(mt0, __shfl_xor_sync(0xffffffffu, mt0, 2));
        mt1 = fmaxf(mt1, __shfl_xor_sync(0xffffffffu, mt1, 1));
        mt1 = fmaxf(mt1, __shfl_xor_sync(0xffffffffu, mt1, 2));
        float mn0 = fmaxf(mrow0, mt0), mn1 = fmaxf(mrow1, mt1);
        float c0 = fexp(mrow0 - mn0), c1 = fexp(mrow1 - mn1);
        lrow0 *= c0; lrow1 *= c1;
        #pragma unroll
        for (int nb = 0; nb < 8; nb++) {
            accO[nb][0] *= c0; accO[nb][1] *= c0;
            accO[nb][2] *= c1; accO[nb][3] *= c1;
        }
        #pragma unroll
        for (int nb = 0; nb < 8; nb++) {
            s[nb][0] = fexp(s[nb][0] - mn0);
            s[nb][1] = fexp(s[nb][1] - mn0);
            s[nb][2] = fexp(s[nb][2] - mn1);
            s[nb][3] = fexp(s[nb][3] - mn1);
            lrow0 += s[nb][0] + s[nb][1];
            lrow1 += s[nb][2] + s[nb][3];
        }
        mrow0 = mn0; mrow1 = mn1;

        // ---- O += P V (product-major schedule) ----
        #pragma unroll
        for (int kb = 0; kb < 4; kb++) {
            uint32_t ph[4], pl[4];
            {
                int ne = 2*kb, no = 2*kb + 1;
                __nv_bfloat162 H;
                H = __floats2bfloat162_rn(s[ne][0], s[ne][1]);
                ph[0] = *reinterpret_cast<uint32_t*>(&H);
                pl[0] = pack_bf16x2(s[ne][0] - __low2float(H), s[ne][1] - __high2float(H));
                H = __floats2bfloat162_rn(s[ne][2], s[ne][3]);
                ph[1] = *reinterpret_cast<uint32_t*>(&H);
                pl[1] = pack_bf16x2(s[ne][2] - __low2float(H), s[ne][3] - __high2float(H));
                H = __floats2bfloat162_rn(s[no][0], s[no][1]);
                ph[2] = *reinterpret_cast<uint32_t*>(&H);
                pl[2] = pack_bf16x2(s[no][0] - __low2float(H), s[no][1] - __high2float(H));
                H = __floats2bfloat162_rn(s[no][2], s[no][3]);
                ph[3] = *reinterpret_cast<uint32_t*>(&H);
                pl[3] = pack_bf16x2(s[no][2] - __low2float(H), s[no][3] - __high2float(H));
            }
            uint32_t vfh[8][2], vfl[8][2];
            #pragma unroll
            for (int db2 = 0; db2 < 4; db2++) {
                uint32_t va = sb + bufo + vfo + (uint32_t)(kb*16*FT_STRIDE + db2*32);
                LDSM_X4_T(vfh[2*db2][0], vfh[2*db2][1], vfh[2*db2+1][0], vfh[2*db2+1][1], va + FS_VH);
                LDSM_X4_T(vfl[2*db2][0], vfl[2*db2][1], vfl[2*db2+1][0], vfl[2*db2+1][1], va + FS_VL);
            }
            #pragma unroll
            for (int db = 0; db < 8; db++)
                MMA_BF16(accO[db], ph, vfh[db]);
            #pragma unroll
            for (int db = 0; db < 8; db++)
                MMA_BF16(accO[db], ph, vfl[db]);
            #pragma unroll
            for (int db = 0; db < 8; db++)
                MMA_BF16(accO[db], pl, vfh[db]);
        }

        __syncthreads();
        if (jt + 2 < 16) issue_tile(jt + 2, bufo);
        CP_COMMIT();
    }

    // ---- finalize ----
    lrow0 += __shfl_xor_sync(0xffffffffu, lrow0, 1);
    lrow0 += __shfl_xor_sync(0xffffffffu, lrow0, 2);
    lrow1 += __shfl_xor_sync(0xffffffffu, lrow1, 1);
    lrow1 += __shfl_xor_sync(0xffffffffu, lrow1, 2);
    float inv0 = 1.f / lrow0, inv1 = 1.f / lrow1;

    size_t r0 = (size_t)(b*TT + i0 + w*16 + gid) * CC + h * DD;
    size_t r1 = r0 + 8 * CC;
    #pragma unroll
    for (int nb = 0; nb < 8; nb++) {
        int col = nb*8 + tig*2;
        float o00 = accO[nb][0]*inv0, o01 = accO[nb][1]*inv0;
        float o10 = accO[nb][2]*inv1, o11 = accO[nb][3]*inv1;
        __nv_bfloat162 H0 = __floats2bfloat162_rn(o00, o01);
        __nv_bfloat162 H1 = __floats2bfloat162_rn(o10, o11);
        *(__nv_bfloat162*)(oh + r0 + col) = H0;
        *(__nv_bfloat162*)(oh + r1 + col) = H1;
        *(__nv_bfloat162*)(ol + r0 + col) =
            __floats2bfloat162_rn(o00 - __low2float(H0), o01 - __high2float(H0));
        *(__nv_bfloat162*)(ol + r1 + col) =
            __floats2bfloat162_rn(o10 - __low2float(H1), o11 - __high2float(H1));
    }
}

// ---------------- launch ----------------
extern "C" void kernel_launch(void* const* d_in, const int* in_sizes, int n_in,
                              void* d_out, int out_size)
{
    const float* x      = (const float*)d_in[0];
    const float* pair   = (const float*)d_in[1];
    const void*  mask   = d_in[2];
    const float* norm_w = (const float*)d_in[3];
    const float* norm_b = (const float*)d_in[4];
    const float* qkv_w  = (const float*)d_in[5];
    const float* qkv_b  = (const float*)d_in[6];
    const float* qln_w  = (const float*)d_in[7];
    const float* qln_b  = (const float*)d_in[8];
    const float* kln_w  = (const float*)d_in[9];
    const float* kln_b  = (const float*)d_in[10];
    const float* proj_w = (const float*)d_in[11];
    const float* proj_b = (const float*)d_in[12];
    float* out = (float*)d_out;

    float *qkvp;
    __nv_bfloat16 *ah, *al, *wh, *wl, *qh, *ql, *kh, *kl, *vh, *vl;
    cudaGetSymbolAddress((void**)&qkvp, g_qkv);
    cudaGetSymbolAddress((void**)&ah, g_ah);
    cudaGetSymbolAddress((void**)&al, g_al);
    cudaGetSymbolAddress((void**)&wh, g_wh);
    cudaGetSymbolAddress((void**)&wl, g_wl);
    cudaGetSymbolAddress((void**)&qh, g_qh);
    cudaGetSymbolAddress((void**)&ql, g_ql);
    cudaGetSymbolAddress((void**)&kh, g_kh);
    cudaGetSymbolAddress((void**)&kl, g_kl);
    cudaGetSymbolAddress((void**)&vh, g_vh);
    cudaGetSymbolAddress((void**)&vl, g_vl);

    cudaFuncSetAttribute(flash_hmma, cudaFuncAttributeMaxDynamicSharedMemorySize, FSM_TOT);
    cudaFuncSetAttribute(gemm_tc16, cudaFuncAttributeMaxDynamicSharedMemorySize, GSMEM);

    // 0. mask dtype detection (front of stream)
    detect_mask_kind<<<1, 256>>>(mask);
    // 1. pre-norm + bf16 split
    ln_split_kernel<<<NROWS, 128>>>(x, norm_w, norm_b, ah, al);
    // 2. split qkv weights + QKV GEMM (HMMA)
    split_kernel<<<(C3*CC/4 + 255)/256, 256>>>(qkv_w, wh, wl, C3*CC/4);
    gemm_tc16<<<dim3(C3/128, NROWS/128), 256, GSMEM>>>(ah, al, wh, wl, qkv_b, qkvp, C3, CC);
    // 3. q/k LN + scale fold + bf16 splits (fused)
    qkv_post<<<NROWS, 128>>>(qkvp, qln_w, qln_b, kln_w, kln_b);
    // 4. pair transpose with mask fold
    bias_transpose_kernel<<<dim3(TT/128, TT, BB), 256>>>(pair, mask);
    // 5. HMMA flash attention -> bf16 hi/lo directly
    flash_hmma<<<dim3(TT/64, BB*HH), 128, FSM_TOT>>>(qh, ql, kh, kl, vh, vl, ah, al);
    // 6. output projection (HMMA)
    split_kernel<<<(CC*CC/4 + 255)/256, 256>>>(proj_w, wh, wl, CC*CC/4);
    gemm_tc16<<<dim3(CC/128, NROWS/128), 256, GSMEM>>>(ah, al, wh, wl, proj_b, out, CC, CC);
}

// round 8
// speedup vs baseline: 1.4942x; 1.4579x over previous
#include <cuda_runtime.h>
#include <cuda_fp16.h>
#include <cstdint>

// Problem constants
#define BB 4
#define TT 1024
#define CC 512
#define HH 8
#define DD 64
#define NROWS (BB*TT)          // 4096
#define C3 (3*CC)              // 1536
#define NEGF (-3.402823466e38f)

// -------- scratch (static device globals; allocation-free) --------
__device__ float g_qkv[(size_t)NROWS*C3];         // 24 MB
__device__ float g_biasT[(size_t)BB*HH*TT*TT];    // 128 MB
__device__ int   g_mask_kind;
__device__ __half g_ah[(size_t)NROWS*CC];         // GEMM A / attn out (fp16)
__device__ __half g_wh[(size_t)C3*CC];            // weights fp16
__device__ __half g_qh[(size_t)NROWS*CC];
__device__ __half g_kh[(size_t)NROWS*CC];
__device__ __half g_vh[(size_t)NROWS*CC];

// ================ generic-PTX helpers ================
__device__ __forceinline__ uint32_t smem_u32(const void* p) {
    uint32_t a;
    asm("{ .reg .u64 t; cvta.to.shared.u64 t, %1; cvt.u32.u64 %0, t; }"
        : "=r"(a) : "l"(p));
    return a;
}
#define LDSM_X4(r0, r1, r2, r3, addr) \
    asm volatile("ldmatrix.sync.aligned.m8n8.x4.shared.b16 {%0,%1,%2,%3}, [%4];" \
        : "=r"(r0), "=r"(r1), "=r"(r2), "=r"(r3) : "r"(addr))
#define LDSM_X4_T(r0, r1, r2, r3, addr) \
    asm volatile("ldmatrix.sync.aligned.m8n8.x4.trans.shared.b16 {%0,%1,%2,%3}, [%4];" \
        : "=r"(r0), "=r"(r1), "=r"(r2), "=r"(r3) : "r"(addr))
#define MMA_F16(d, a, b) \
    asm volatile("mma.sync.aligned.m16n8k16.row.col.f32.f16.f16.f32 " \
        "{%0,%1,%2,%3}, {%4,%5,%6,%7}, {%8,%9}, {%0,%1,%2,%3};" \
        : "+f"((d)[0]), "+f"((d)[1]), "+f"((d)[2]), "+f"((d)[3]) \
        : "r"((a)[0]), "r"((a)[1]), "r"((a)[2]), "r"((a)[3]), \
          "r"((b)[0]), "r"((b)[1]))
#define CP_ASYNC16(saddr, gptr) \
    asm volatile("cp.async.cg.shared.global [%0], [%1], 16;" \
        :: "r"(saddr), "l"(gptr))
#define CP_COMMIT() asm volatile("cp.async.commit_group;" ::: "memory")
#define CP_WAIT1()  asm volatile("cp.async.wait_group 1;" ::: "memory")

// fast exp on FMA pipe
__device__ __forceinline__ float fexp(float x) {
    float t = fmaxf(x * 1.4426950408889634f, -126.f);
    float fi = floorf(t);
    float f = t - fi;
    float p = 1.5403530393381609e-4f;
    p = fmaf(p, f, 1.3333558146428443e-3f);
    p = fmaf(p, f, 9.6181291976036826e-3f);
    p = fmaf(p, f, 5.5504108664821580e-2f);
    p = fmaf(p, f, 2.4022650695910071e-1f);
    p = fmaf(p, f, 6.9314718055994531e-1f);
    p = fmaf(p, f, 1.0f);
    int ii = (int)fi;
    return p * __int_as_float((ii + 127) << 23);
}

// ================ LayerNorm core ================
__device__ __forceinline__ float warp_sum(float v) {
    #pragma unroll
    for (int o = 16; o; o >>= 1) v += __shfl_xor_sync(0xffffffffu, v, o);
    return v;
}

__device__ __forceinline__ void ln_core(float4& v, const float* w, const float* b,
                                        int t, float4& o)
{
    float s  = v.x + v.y + v.z + v.w;
    float sq = v.x*v.x + v.y*v.y + v.z*v.z + v.w*v.w;
    s = warp_sum(s); sq = warp_sum(sq);
    __shared__ float sh[8];
    int wid = t >> 5, lid = t & 31;
    if (lid == 0) { sh[wid] = s; sh[4 + wid] = sq; }
    __syncthreads();
    float ts = sh[0] + sh[1] + sh[2] + sh[3];
    float tq = sh[4] + sh[5] + sh[6] + sh[7];
    float mean = ts * (1.f / CC);
    float var  = tq * (1.f / CC) - mean * mean;
    float rstd = rsqrtf(var + 1e-5f);
    float4 wv = *(const float4*)(w + t * 4);
    float4 bv = *(const float4*)(b + t * 4);
    o.x = (v.x - mean) * rstd * wv.x + bv.x;
    o.y = (v.y - mean) * rstd * wv.y + bv.y;
    o.z = (v.z - mean) * rstd * wv.z + bv.z;
    o.w = (v.w - mean) * rstd * wv.w + bv.w;
}

__device__ __forceinline__ void h_store4(float4 o, __half* dst, size_t base)
{
    *(__half2*)(dst + base)     = __floats2half2_rn(o.x, o.y);
    *(__half2*)(dst + base + 2) = __floats2half2_rn(o.z, o.w);
}

// LN + fp16 convert (pre-norm x)
__global__ void ln_h_kernel(const float* src, const float* __restrict__ w,
                            const float* __restrict__ b, __half* dst)
{
    int row = blockIdx.x, t = threadIdx.x;
    float4 v = *(const float4*)(src + (size_t)row * CC + t * 4);
    float4 o;
    ln_core(v, w, b, t, o);
    h_store4(o, dst, (size_t)row * CC + t * 4);
}

// post-QKV: q-LN(+scale)+cvt, k-LN+cvt, v cvt
__global__ void qkv_post(const float* __restrict__ qkv,
                         const float* __restrict__ qw, const float* __restrict__ qb,
                         const float* __restrict__ kw, const float* __restrict__ kb)
{
    int row = blockIdx.x, t = threadIdx.x;
    const float* rp = qkv + (size_t)row * C3;
    size_t base = (size_t)row * CC + t * 4;
    float4 v = *(const float4*)(rp + t * 4);
    float4 o;
    ln_core(v, qw, qb, t, o);
    o.x *= 0.125f; o.y *= 0.125f; o.z *= 0.125f; o.w *= 0.125f;
    h_store4(o, g_qh, base);
    __syncthreads();
    v = *(const float4*)(rp + CC + t * 4);
    ln_core(v, kw, kb, t, o);
    h_store4(o, g_kh, base);
    v = *(const float4*)(rp + 2 * CC + t * 4);
    h_store4(v, g_vh, base);
}

// fp32 -> fp16 convert (vec4)
__global__ void cvt_kernel(const float* __restrict__ src, __half* dst, int n4)
{
    int i = blockIdx.x * blockDim.x + threadIdx.x;
    if (i >= n4) return;
    float4 v = ((const float4*)src)[i];
    h_store4(v, dst, (size_t)i * 4);
}

// ================ HMMA fp16 single-pass GEMM ================
// C[m,n] = sum_k A[m,k]*B[n,k] + bias[n]
#define GT_STRIDE 80
#define GT_TILE   (128*GT_STRIDE)       // 10240
#define G_A 0
#define G_B GT_TILE
#define GBUF  (2*GT_TILE)               // 20480 per buffer
#define GSMEM (2*GBUF)                  // 40960

__global__ __launch_bounds__(256, 2)
void gemm_tc16(const __half* __restrict__ A, const __half* __restrict__ B,
               const float* __restrict__ bias, float* __restrict__ C,
               int N, int K)
{
    extern __shared__ __align__(16) char smem[];
    uint32_t sb = smem_u32(smem);

    int tid = threadIdx.x;
    int wid = tid >> 5, lane = tid & 31;
    int wm = wid >> 1, wn = wid & 1;
    int gid = lane >> 2, tig = lane & 3;
    int m0 = blockIdx.y * 128, n0 = blockIdx.x * 128;

    float acc[2][8][4];
    #pragma unroll
    for (int i = 0; i < 2; i++)
        #pragma unroll
        for (int j = 0; j < 8; j++)
            #pragma unroll
            for (int c = 0; c < 4; c++) acc[i][j][c] = 0.f;

    int lrow = tid >> 1, ls0 = (tid & 1) * 2;   // row 0..127, segs {0,1} or {2,3}

    auto issue = [&](int kc0, uint32_t bufo) {
        #pragma unroll
        for (int i = 0; i < 2; i++) {
            int seg = ls0 + i;                 // 16B seg within 64B row
            size_t ga = (size_t)(m0 + lrow) * K + kc0 + seg * 8;
            size_t gb = (size_t)(n0 + lrow) * K + kc0 + seg * 8;
            uint32_t so = sb + bufo + (uint32_t)(lrow * GT_STRIDE + seg * 16);
            CP_ASYNC16(so + G_A, A + ga);
            CP_ASYNC16(so + G_B, B + gb);
        }
    };

    int sub = lane >> 3, rin = lane & 7;
    uint32_t aoff = (uint32_t)((wm*32 + (sub & 1)*8 + rin) * GT_STRIDE + (sub >> 1) * 16);
    uint32_t boff = (uint32_t)((wn*64 + (sub >> 1)*8 + rin) * GT_STRIDE + (sub & 1) * 16);

    int nch = K >> 5;
    issue(0, 0); CP_COMMIT();
    issue(32, GBUF); CP_COMMIT();

    for (int ch = 0; ch < nch; ch++) {
        uint32_t bufo = (uint32_t)(ch & 1) * GBUF;
        CP_WAIT1();
        __syncthreads();

        #pragma unroll
        for (int ks = 0; ks < 2; ks++) {
            uint32_t fA[2][4];
            #pragma unroll
            for (int am = 0; am < 2; am++) {
                uint32_t ad = sb + bufo + G_A + aoff + am * (16 * GT_STRIDE) + ks * 32;
                LDSM_X4(fA[am][0], fA[am][1], fA[am][2], fA[am][3], ad);
            }
            uint32_t fB[8][2];
            #pragma unroll
            for (int bg = 0; bg < 4; bg++) {
                uint32_t bd = sb + bufo + G_B + boff + bg * (16 * GT_STRIDE) + ks * 32;
                LDSM_X4(fB[2*bg][0], fB[2*bg][1], fB[2*bg+1][0], fB[2*bg+1][1], bd);
            }
            #pragma unroll
            for (int am = 0; am < 2; am++)
                #pragma unroll
                for (int nb = 0; nb < 8; nb++)
                    MMA_F16(acc[am][nb], fA[am], fB[nb]);
        }
        __syncthreads();
        if (ch + 2 < nch) issue((ch + 2) << 5, bufo);
        CP_COMMIT();
    }

    #pragma unroll
    for (int am = 0; am < 2; am++) {
        int row = m0 + wm*32 + am*16 + gid;
        #pragma unroll
        for (int nb = 0; nb < 8; nb++) {
            int col = n0 + wn*64 + nb*8 + tig*2;
            float2 bv = *(const float2*)(bias + col);
            float2 o0 = { acc[am][nb][0] + bv.x, acc[am][nb][1] + bv.y };
            float2 o1 = { acc[am][nb][2] + bv.x, acc[am][nb][3] + bv.y };
            *(float2*)(C + (size_t)row * N + col)       = o0;
            *(float2*)(C + (size_t)(row + 8) * N + col) = o1;
        }
    }
}

// ---------------- mask dtype detection ----------------
__global__ void detect_mask_kind(const void* mask)
{
    __shared__ int s_int, s_float;
    if (threadIdx.x == 0) { s_int = 1; s_float = 1; }
    __syncthreads();
    const unsigned int* w = (const unsigned int*)mask;
    int ok_i = 1, ok_f = 1;
    for (int i = threadIdx.x; i < 1024; i += blockDim.x) {
        unsigned int v = w[i];
        if (v > 1u) ok_i = 0;
        if (v != 0u && v != 0x3F800000u) ok_f = 0;
    }
    atomicAnd(&s_int, ok_i);
    atomicAnd(&s_float, ok_f);
    __syncthreads();
    if (threadIdx.x == 0) g_mask_kind = s_int ? 0 : (s_float ? 1 : 2);
}

// ---------------- pair [B,T,T,H] -> biasT [B,H,T,T], folding mask ----------------
__global__ void bias_transpose_kernel(const float* __restrict__ pair,
                                      const void* __restrict__ mask)
{
    __shared__ float sp[128][9];
    __shared__ float addm[128];
    int b = blockIdx.z, i = blockIdx.y, j0 = blockIdx.x * 128;
    int t = threadIdx.x;

    const float* src = pair + (((size_t)(b * TT + i) * TT) + j0) * HH;
    {
        int f = t * 4;
        int tj = f >> 3;
        int h0 = f & 7;
        float4 v = *(const float4*)(src + f);
        sp[tj][h0]   = v.x; sp[tj][h0+1] = v.y;
        sp[tj][h0+2] = v.z; sp[tj][h0+3] = v.w;
    }
    if (t < 128) {
        size_t mi = ((size_t)(b * TT + i)) * TT + j0 + t;
        int kind = g_mask_kind;
        bool mv;
        if (kind == 0)      mv = ((const int*)mask)[mi] != 0;
        else if (kind == 1) mv = ((const float*)mask)[mi] != 0.f;
        else                mv = ((const unsigned char*)mask)[mi] != 0;
        addm[t] = mv ? 0.f : NEGF;
    }
    __syncthreads();
    #pragma unroll
    for (int u = 0; u < 4; u++) {
        int f = t + 256 * u;
        int h = f >> 7;
        int tj = f & 127;
        g_biasT[(((size_t)(b * HH + h) * TT + i) * TT) + j0 + tj] = sp[tj][h] + addm[tj];
    }
}

// ================ HMMA fp16 flash attention, cp.async double-buffered ================
#define FT_STRIDE 144
#define FS_K 0
#define FS_V 9216
#define FS_BIAS 18432
#define FB_STRIDE 272
#define FBUF (18432 + 64*FB_STRIDE)     // 35840 per buffer
#define FSM_TOT (2*FBUF)                // 71680

__global__ __launch_bounds__(128, 3)
void flash_hmma(const __half* __restrict__ qh, const __half* __restrict__ kh,
                const __half* __restrict__ vh, __half* __restrict__ oh)
{
    extern __shared__ __align__(16) char sm[];
    uint32_t sb = smem_u32(sm);
    int tid = threadIdx.x;
    int w = tid >> 5, lane = tid & 31;
    int gid = lane >> 2, tig = lane & 3;
    int sub = lane >> 3, rin = lane & 7;
    int bh = blockIdx.y;
    int b = bh >> 3, h = bh & 7;
    int i0 = blockIdx.x * 64;

    // ---- stage Q tile into FS_K slot, extract A-fragments ----
    const __half* qhp = qh + ((size_t)(b*TT + i0)) * CC + h * DD;
    #pragma unroll
    for (int u = 0; u < 4; u++) {
        int f = u * 128 + tid;
        int row = f >> 3, seg = f & 7;
        *(float4*)(sm + FS_K + row*FT_STRIDE + seg*16) = *(const float4*)(qhp + (size_t)row*CC + seg*8);
    }
    __syncthreads();
    uint32_t qf[4][4];
    {
        uint32_t qa = sb + FS_K + (uint32_t)((w*16 + (sub & 1)*8 + rin) * FT_STRIDE + (sub >> 1)*16);
        #pragma unroll
        for (int kb = 0; kb < 4; kb++)
            LDSM_X4(qf[kb][0], qf[kb][1], qf[kb][2], qf[kb][3], qa + kb*32);
    }
    __syncthreads();

    float accO[8][4];
    #pragma unroll
    for (int nb = 0; nb < 8; nb++)
        #pragma unroll
        for (int c = 0; c < 4; c++) accO[nb][c] = 0.f;
    float mrow0 = -3.0e38f, mrow1 = -3.0e38f;
    float lrow0 = 0.f, lrow1 = 0.f;

    const __half* khp = kh + ((size_t)(b*TT)) * CC + h * DD;
    const __half* vhp = vh + ((size_t)(b*TT)) * CC + h * DD;
    const float* bbase = g_biasT + ((size_t)bh * TT + i0) * TT;

    auto issue_tile = [&](int jt, uint32_t bufo) {
        int j0 = jt * 64;
        #pragma unroll
        for (int u = 0; u < 4; u++) {
            int f = u * 128 + tid;
            int row = f >> 3, seg = f & 7;
            size_t g = (size_t)(j0 + row) * CC + seg * 8;
            uint32_t so = sb + bufo + (uint32_t)(row*FT_STRIDE + seg*16);
            CP_ASYNC16(so + FS_K, khp + g);
            CP_ASYNC16(so + FS_V, vhp + g);
        }
        #pragma unroll
        for (int u = 0; u < 8; u++) {
            int f = u * 128 + tid;
            int row = f >> 4, seg = f & 15;
            CP_ASYNC16(sb + bufo + FS_BIAS + (uint32_t)(row*FB_STRIDE + seg*16),
                       bbase + (size_t)row*TT + j0 + seg*4);
        }
    };

    uint32_t kfo = (uint32_t)(((sub >> 1)*8 + rin) * FT_STRIDE + (sub & 1)*16);
    uint32_t vfo = (uint32_t)(((sub & 1)*8 + rin) * FT_STRIDE + (sub >> 1)*16);

    issue_tile(0, 0); CP_COMMIT();
    issue_tile(1, FBUF); CP_COMMIT();

    for (int jt = 0; jt < 16; jt++) {
        uint32_t bufo = (uint32_t)(jt & 1) * FBUF;
        CP_WAIT1();
        __syncthreads();

        // ---- S = Q K^T + bias ----
        float s[8][4];
        #pragma unroll
        for (int nb = 0; nb < 8; nb++) {
            int brow = w*16 + gid;
            int bcol = (nb*8 + tig*2) * 4;
            float2 b0 = *(const float2*)(sm + bufo + FS_BIAS + brow*FB_STRIDE + bcol);
            float2 b1 = *(const float2*)(sm + bufo + FS_BIAS + (brow+8)*FB_STRIDE + bcol);
            s[nb][0] = b0.x; s[nb][1] = b0.y; s[nb][2] = b1.x; s[nb][3] = b1.y;
        }
        #pragma unroll
        for (int kb = 0; kb < 4; kb++) {
            uint32_t kf[8][2];
            #pragma unroll
            for (int nb2 = 0; nb2 < 4; nb2++) {
                uint32_t ka = sb + bufo + FS_K + kfo + (uint32_t)(nb2*16*FT_STRIDE + kb*32);
                LDSM_X4(kf[2*nb2][0], kf[2*nb2][1], kf[2*nb2+1][0], kf[2*nb2+1][1], ka);
            }
            #pragma unroll
            for (int nb = 0; nb < 8; nb++)
                MMA_F16(s[nb], qf[kb], kf[nb]);
        }

        // ---- online softmax ----
        float mt0 = s[0][0], mt1 = s[0][2];
        #pragma unroll
        for (int nb = 0; nb < 8; nb++) {
            mt0 = fmaxf(mt0, fmaxf(s[nb][0], s[nb][1]));
            mt1 = fmaxf(mt1, fmaxf(s[nb][2], s[nb][3]));
        }
        mt0 = fmaxf(mt0, __shfl_xor_sync(0xffffffffu, mt0, 1));
        mt0 = fmaxf(mt0, __shfl_xor_sync(0xffffffffu, mt0, 2));
        mt1 = fmaxf(mt1, __shfl_xor_sync(0xffffffffu, mt1, 1));
        mt1 = fmaxf(mt1, __shfl_xor_sync(0xffffffffu, mt1, 2));
        float mn0 = fmaxf(mrow0, mt0), mn1 = fmaxf(mrow1, mt1);
        float c0 = fexp(mrow0 - mn0), c1 = fexp(mrow1 - mn1);
        lrow0 *= c0; lrow1 *= c1;
        #pragma unroll
        for (int nb = 0; nb < 8; nb++) {
            accO[nb][0] *= c0; accO[nb][1] *= c0;
            accO[nb][2] *= c1; accO[nb][3] *= c1;
        }
        #pragma unroll
        for (int nb = 0; nb < 8; nb++) {
            s[nb][0] = fexp(s[nb][0] - mn0);
            s[nb][1] = fexp(s[nb][1] - mn0);
            s[nb][2] = fexp(s[nb][2] - mn1);
            s[nb][3] = fexp(s[nb][3] - mn1);
            lrow0 += s[nb][0] + s[nb][1];
            lrow1 += s[nb][2] + s[nb][3];
        }
        mrow0 = mn0; mrow1 = mn1;

        // ---- O += P V ----
        #pragma unroll
        for (int kb = 0; kb < 4; kb++) {
            uint32_t ph[4];
            {
                int ne = 2*kb, no = 2*kb + 1;
                __half2 H;
                H = __floats2half2_rn(s[ne][0], s[ne][1]); ph[0] = *reinterpret_cast<uint32_t*>(&H);
                H = __floats2half2_rn(s[ne][2], s[ne][3]); ph[1] = *reinterpret_cast<uint32_t*>(&H);
                H = __floats2half2_rn(s[no][0], s[no][1]); ph[2] = *reinterpret_cast<uint32_t*>(&H);
                H = __floats2half2_rn(s[no][2], s[no][3]); ph[3] = *reinterpret_cast<uint32_t*>(&H);
            }
            uint32_t vf[8][2];
            #pragma unroll
            for (int db2 = 0; db2 < 4; db2++) {
                uint32_t va = sb + bufo + FS_V + vfo + (uint32_t)(kb*16*FT_STRIDE + db2*32);
                LDSM_X4_T(vf[2*db2][0], vf[2*db2][1], vf[2*db2+1][0], vf[2*db2+1][1], va);
            }
            #pragma unroll
            for (int db = 0; db < 8; db++)
                MMA_F16(accO[db], ph, vf[db]);
        }

        __syncthreads();
        if (jt + 2 < 16) issue_tile(jt + 2, bufo);
        CP_COMMIT();
    }

    // ---- finalize ----
    lrow0 += __shfl_xor_sync(0xffffffffu, lrow0, 1);
    lrow0 += __shfl_xor_sync(0xffffffffu, lrow0, 2);
    lrow1 += __shfl_xor_sync(0xffffffffu, lrow1, 1);
    lrow1 += __shfl_xor_sync(0xffffffffu, lrow1, 2);
    float inv0 = 1.f / lrow0, inv1 = 1.f / lrow1;

    size_t r0 = (size_t)(b*TT + i0 + w*16 + gid) * CC + h * DD;
    size_t r1 = r0 + 8 * CC;
    #pragma unroll
    for (int nb = 0; nb < 8; nb++) {
        int col = nb*8 + tig*2;
        *(__half2*)(oh + r0 + col) = __floats2half2_rn(accO[nb][0]*inv0, accO[nb][1]*inv0);
        *(__half2*)(oh + r1 + col) = __floats2half2_rn(accO[nb][2]*inv1, accO[nb][3]*inv1);
    }
}

// ---------------- launch ----------------
extern "C" void kernel_launch(void* const* d_in, const int* in_sizes, int n_in,
                              void* d_out, int out_size)
{
    const float* x      = (const float*)d_in[0];
    const float* pair   = (const float*)d_in[1];
    const void*  mask   = d_in[2];
    const float* norm_w = (const float*)d_in[3];
    const float* norm_b = (const float*)d_in[4];
    const float* qkv_w  = (const float*)d_in[5];
    const float* qkv_b  = (const float*)d_in[6];
    const float* qln_w  = (const float*)d_in[7];
    const float* qln_b  = (const float*)d_in[8];
    const float* kln_w  = (const float*)d_in[9];
    const float* kln_b  = (const float*)d_in[10];
    const float* proj_w = (const float*)d_in[11];
    const float* proj_b = (const float*)d_in[12];
    float* out = (float*)d_out;

    float *qkvp;
    __half *ah, *wh, *qh, *kh, *vh;
    cudaGetSymbolAddress((void**)&qkvp, g_qkv);
    cudaGetSymbolAddress((void**)&ah, g_ah);
    cudaGetSymbolAddress((void**)&wh, g_wh);
    cudaGetSymbolAddress((void**)&qh, g_qh);
    cudaGetSymbolAddress((void**)&kh, g_kh);
    cudaGetSymbolAddress((void**)&vh, g_vh);

    cudaFuncSetAttribute(flash_hmma, cudaFuncAttributeMaxDynamicSharedMemorySize, FSM_TOT);
    cudaFuncSetAttribute(gemm_tc16, cudaFuncAttributeMaxDynamicSharedMemorySize, GSMEM);

    // 0. mask dtype detection (front of stream)
    detect_mask_kind<<<1, 256>>>(mask);
    // 1. pre-norm + fp16 convert
    ln_h_kernel<<<NROWS, 128>>>(x, norm_w, norm_b, ah);
    // 2. convert qkv weights + QKV GEMM (HMMA fp16)
    cvt_kernel<<<(C3*CC/4 + 255)/256, 256>>>(qkv_w, wh, C3*CC/4);
    gemm_tc16<<<dim3(C3/128, NROWS/128), 256, GSMEM>>>(ah, wh, qkv_b, qkvp, C3, CC);
    // 3. q/k LN + scale fold + fp16 converts (fused)
    qkv_post<<<NROWS, 128>>>(qkvp, qln_w, qln_b, kln_w, kln_b);
    // 4. pair transpose with mask fold
    bias_transpose_kernel<<<dim3(TT/128, TT, BB), 256>>>(pair, mask);
    // 5. fp16 flash attention -> fp16 out (reuse ah)
    flash_hmma<<<dim3(TT/64, BB*HH), 128, FSM_TOT>>>(qh, kh, vh, ah);
    // 6. output projection (HMMA fp16)
    cvt_kernel<<<(CC*CC/4 + 255)/256, 256>>>(proj_w, wh, CC*CC/4);
    gemm_tc16<<<dim3(CC/128, NROWS/128), 256, GSMEM>>>(ah, wh, proj_b, out, CC, CC);
}

// round 10
// speedup vs baseline: 1.5383x; 1.0295x over previous
#include <cuda_runtime.h>
#include <cuda_fp16.h>
#include <cstdint>

// Problem constants
#define BB 4
#define TT 1024
#define CC 512
#define HH 8
#define DD 64
#define NROWS (BB*TT)          // 4096
#define C3 (3*CC)              // 1536
#define NEGF (-3.402823466e38f)

// -------- scratch (static device globals; allocation-free) --------
__device__ float g_qkv[(size_t)NROWS*C3];         // 24 MB
__device__ float g_biasT[(size_t)BB*HH*TT*TT];    // 128 MB
__device__ int   g_mask_kind;
__device__ __half g_ah[(size_t)NROWS*CC];         // GEMM A / attn out (fp16)
__device__ __half g_wh[(size_t)C3*CC];            // weights fp16
__device__ __half g_qh[(size_t)NROWS*CC];
__device__ __half g_kh[(size_t)NROWS*CC];
__device__ __half g_vh[(size_t)NROWS*CC];

// ================ generic-PTX helpers ================
__device__ __forceinline__ uint32_t smem_u32(const void* p) {
    uint32_t a;
    asm("{ .reg .u64 t; cvta.to.shared.u64 t, %1; cvt.u32.u64 %0, t; }"
        : "=r"(a) : "l"(p));
    return a;
}
#define LDSM_X4(r0, r1, r2, r3, addr) \
    asm volatile("ldmatrix.sync.aligned.m8n8.x4.shared.b16 {%0,%1,%2,%3}, [%4];" \
        : "=r"(r0), "=r"(r1), "=r"(r2), "=r"(r3) : "r"(addr))
#define LDSM_X4_T(r0, r1, r2, r3, addr) \
    asm volatile("ldmatrix.sync.aligned.m8n8.x4.trans.shared.b16 {%0,%1,%2,%3}, [%4];" \
        : "=r"(r0), "=r"(r1), "=r"(r2), "=r"(r3) : "r"(addr))
#define MMA_F16(d, a, b) \
    asm volatile("mma.sync.aligned.m16n8k16.row.col.f32.f16.f16.f32 " \
        "{%0,%1,%2,%3}, {%4,%5,%6,%7}, {%8,%9}, {%0,%1,%2,%3};" \
        : "+f"((d)[0]), "+f"((d)[1]), "+f"((d)[2]), "+f"((d)[3]) \
        : "r"((a)[0]), "r"((a)[1]), "r"((a)[2]), "r"((a)[3]), \
          "r"((b)[0]), "r"((b)[1]))
#define CP_ASYNC16(saddr, gptr) \
    asm volatile("cp.async.cg.shared.global [%0], [%1], 16;" \
        :: "r"(saddr), "l"(gptr))
#define CP_COMMIT() asm volatile("cp.async.commit_group;" ::: "memory")
#define CP_WAIT1()  asm volatile("cp.async.wait_group 1;" ::: "memory")

// fast exp on FMA pipe
__device__ __forceinline__ float fexp(float x) {
    float t = fmaxf(x * 1.4426950408889634f, -126.f);
    float fi = floorf(t);
    float f = t - fi;
    float p = 1.5403530393381609e-4f;
    p = fmaf(p, f, 1.3333558146428443e-3f);
    p = fmaf(p, f, 9.6181291976036826e-3f);
    p = fmaf(p, f, 5.5504108664821580e-2f);
    p = fmaf(p, f, 2.4022650695910071e-1f);
    p = fmaf(p, f, 6.9314718055994531e-1f);
    p = fmaf(p, f, 1.0f);
    int ii = (int)fi;
    return p * __int_as_float((ii + 127) << 23);
}

// ================ LayerNorm core ================
__device__ __forceinline__ float warp_sum(float v) {
    #pragma unroll
    for (int o = 16; o; o >>= 1) v += __shfl_xor_sync(0xffffffffu, v, o);
    return v;
}

__device__ __forceinline__ void ln_core(float4& v, const float* w, const float* b,
                                        int t, float4& o)
{
    float s  = v.x + v.y + v.z + v.w;
    float sq = v.x*v.x + v.y*v.y + v.z*v.z + v.w*v.w;
    s = warp_sum(s); sq = warp_sum(sq);
    __shared__ float sh[8];
    int wid = t >> 5, lid = t & 31;
    if (lid == 0) { sh[wid] = s; sh[4 + wid] = sq; }
    __syncthreads();
    float ts = sh[0] + sh[1] + sh[2] + sh[3];
    float tq = sh[4] + sh[5] + sh[6] + sh[7];
    float mean = ts * (1.f / CC);
    float var  = tq * (1.f / CC) - mean * mean;
    float rstd = rsqrtf(var + 1e-5f);
    float4 wv = *(const float4*)(w + t * 4);
    float4 bv = *(const float4*)(b + t * 4);
    o.x = (v.x - mean) * rstd * wv.x + bv.x;
    o.y = (v.y - mean) * rstd * wv.y + bv.y;
    o.z = (v.z - mean) * rstd * wv.z + bv.z;
    o.w = (v.w - mean) * rstd * wv.w + bv.w;
}

__device__ __forceinline__ void h_store4(float4 o, __half* dst, size_t base)
{
    *(__half2*)(dst + base)     = __floats2half2_rn(o.x, o.y);
    *(__half2*)(dst + base + 2) = __floats2half2_rn(o.z, o.w);
}

__global__ void ln_h_kernel(const float* src, const float* __restrict__ w,
                            const float* __restrict__ b, __half* dst)
{
    int row = blockIdx.x, t = threadIdx.x;
    float4 v = *(const float4*)(src + (size_t)row * CC + t * 4);
    float4 o;
    ln_core(v, w, b, t, o);
    h_store4(o, dst, (size_t)row * CC + t * 4);
}

__global__ void qkv_post(const float* __restrict__ qkv,
                         const float* __restrict__ qw, const float* __restrict__ qb,
                         const float* __restrict__ kw, const float* __restrict__ kb)
{
    int row = blockIdx.x, t = threadIdx.x;
    const float* rp = qkv + (size_t)row * C3;
    size_t base = (size_t)row * CC + t * 4;
    float4 v = *(const float4*)(rp + t * 4);
    float4 o;
    ln_core(v, qw, qb, t, o);
    o.x *= 0.125f; o.y *= 0.125f; o.z *= 0.125f; o.w *= 0.125f;
    h_store4(o, g_qh, base);
    __syncthreads();
    v = *(const float4*)(rp + CC + t * 4);
    ln_core(v, kw, kb, t, o);
    h_store4(o, g_kh, base);
    v = *(const float4*)(rp + 2 * CC + t * 4);
    h_store4(v, g_vh, base);
}

__global__ void cvt_kernel(const float* __restrict__ src, __half* dst, int n4)
{
    int i = blockIdx.x * blockDim.x + threadIdx.x;
    if (i >= n4) return;
    float4 v = ((const float4*)src)[i];
    h_store4(v, dst, (size_t)i * 4);
}

// ================ HMMA fp16 GEMM: 4 warps, warp tile 64x64 ================
#define GT_STRIDE 80
#define GT_TILE   (128*GT_STRIDE)       // 10240
#define G_A 0
#define G_B GT_TILE
#define GBUF  (2*GT_TILE)               // 20480 per buffer
#define GSMEM (2*GBUF)                  // 40960

__global__ __launch_bounds__(128, 2)
void gemm_tc16(const __half* __restrict__ A, const __half* __restrict__ B,
               const float* __restrict__ bias, float* __restrict__ C,
               int N, int K)
{
    extern __shared__ __align__(16) char smem[];
    uint32_t sb = smem_u32(smem);

    int tid = threadIdx.x;
    int wid = tid >> 5, lane = tid & 31;
    int wm = wid >> 1, wn = wid & 1;       // 2x2 warp grid, warp tile 64x64
    int gid = lane >> 2, tig = lane & 3;
    int m0 = blockIdx.y * 128, n0 = blockIdx.x * 128;

    float acc[4][8][4];
    #pragma unroll
    for (int i = 0; i < 4; i++)
        #pragma unroll
        for (int j = 0; j < 8; j++)
            #pragma unroll
            for (int c = 0; c < 4; c++) acc[i][j][c] = 0.f;

    int lrow = tid >> 2, lseg = tid & 3;   // base row 0..31, seg 0..3

    // full tile = 128 rows x 4 segs = 512 float4 per matrix; 128 threads x 4 iters
    auto issue = [&](int kc0, uint32_t bufo) {
        #pragma unroll
        for (int i = 0; i < 4; i++) {
            int row = lrow + i * 32;
            size_t ga = (size_t)(m0 + row) * K + kc0 + lseg * 8;
            size_t gb = (size_t)(n0 + row) * K + kc0 + lseg * 8;
            uint32_t so = sb + bufo + (uint32_t)(row * GT_STRIDE + lseg * 16);
            CP_ASYNC16(so + G_A, A + ga);
            CP_ASYNC16(so + G_B, B + gb);
        }
    };

    int sub = lane >> 3, rin = lane & 7;
    uint32_t aoff = (uint32_t)((wm*64 + (sub & 1)*8 + rin) * GT_STRIDE + (sub >> 1) * 16);
    uint32_t boff = (uint32_t)((wn*64 + (sub >> 1)*8 + rin) * GT_STRIDE + (sub & 1) * 16);

    int nch = K >> 5;
    issue(0, 0); CP_COMMIT();
    issue(32, GBUF); CP_COMMIT();

    for (int ch = 0; ch < nch; ch++) {
        uint32_t bufo = (uint32_t)(ch & 1) * GBUF;
        CP_WAIT1();
        __syncthreads();

        #pragma unroll
        for (int ks = 0; ks < 2; ks++) {
            uint32_t fA[4][4];
            #pragma unroll
            for (int am = 0; am < 4; am++) {
                uint32_t ad = sb + bufo + G_A + aoff + am * (16 * GT_STRIDE) + ks * 32;
                LDSM_X4(fA[am][0], fA[am][1], fA[am][2], fA[am][3], ad);
            }
            uint32_t fB[8][2];
            #pragma unroll
            for (int bg = 0; bg < 4; bg++) {
                uint32_t bd = sb + bufo + G_B + boff + bg * (16 * GT_STRIDE) + ks * 32;
                LDSM_X4(fB[2*bg][0], fB[2*bg][1], fB[2*bg+1][0], fB[2*bg+1][1], bd);
            }
            // product-major: each accumulator touched once per 32-MMA sweep
            #pragma unroll
            for (int am = 0; am < 4; am++)
                #pragma unroll
                for (int nb = 0; nb < 8; nb++)
                    MMA_F16(acc[am][nb], fA[am], fB[nb]);
        }
        __syncthreads();
        if (ch + 2 < nch) issue((ch + 2) << 5, bufo);
        CP_COMMIT();
    }

    #pragma unroll
    for (int am = 0; am < 4; am++) {
        int row = m0 + wm*64 + am*16 + gid;
        #pragma unroll
        for (int nb = 0; nb < 8; nb++) {
            int col = n0 + wn*64 + nb*8 + tig*2;
            float2 bv = *(const float2*)(bias + col);
            float2 o0 = { acc[am][nb][0] + bv.x, acc[am][nb][1] + bv.y };
            float2 o1 = { acc[am][nb][2] + bv.x, acc[am][nb][3] + bv.y };
            *(float2*)(C + (size_t)row * N + col)       = o0;
            *(float2*)(C + (size_t)(row + 8) * N + col) = o1;
        }
    }
}

// ---------------- mask dtype detection ----------------
__global__ void detect_mask_kind(const void* mask)
{
    __shared__ int s_int, s_float;
    if (threadIdx.x == 0) { s_int = 1; s_float = 1; }
    __syncthreads();
    const unsigned int* w = (const unsigned int*)mask;
    int ok_i = 1, ok_f = 1;
    for (int i = threadIdx.x; i < 1024; i += blockDim.x) {
        unsigned int v = w[i];
        if (v > 1u) ok_i = 0;
        if (v != 0u && v != 0x3F800000u) ok_f = 0;
    }
    atomicAnd(&s_int, ok_i);
    atomicAnd(&s_float, ok_f);
    __syncthreads();
    if (threadIdx.x == 0) g_mask_kind = s_int ? 0 : (s_float ? 1 : 2);
}

// ---------------- pair [B,T,T,H] -> biasT [B,H,T,T], folding mask ----------------
__global__ void bias_transpose_kernel(const float* __restrict__ pair,
                                      const void* __restrict__ mask)
{
    __shared__ float sp[128][9];
    __shared__ float addm[128];
    int b = blockIdx.z, i = blockIdx.y, j0 = blockIdx.x * 128;
    int t = threadIdx.x;

    const float* src = pair + (((size_t)(b * TT + i) * TT) + j0) * HH;
    {
        int f = t * 4;
        int tj = f >> 3;
        int h0 = f & 7;
        float4 v = *(const float4*)(src + f);
        sp[tj][h0]   = v.x; sp[tj][h0+1] = v.y;
        sp[tj][h0+2] = v.z; sp[tj][h0+3] = v.w;
    }
    if (t < 128) {
        size_t mi = ((size_t)(b * TT + i)) * TT + j0 + t;
        int kind = g_mask_kind;
        bool mv;
        if (kind == 0)      mv = ((const int*)mask)[mi] != 0;
        else if (kind == 1) mv = ((const float*)mask)[mi] != 0.f;
        else                mv = ((const unsigned char*)mask)[mi] != 0;
        addm[t] = mv ? 0.f : NEGF;
    }
    __syncthreads();
    #pragma unroll
    for (int u = 0; u < 4; u++) {
        int f = t + 256 * u;
        int h = f >> 7;
        int tj = f & 127;
        g_biasT[(((size_t)(b * HH + h) * TT + i) * TT) + j0 + tj] = sp[tj][h] + addm[tj];
    }
}

// ================ HMMA fp16 flash attention: 128 Q rows, warp=32 rows ================
#define FT_STRIDE 144
#define FS_K 0
#define FS_V 9216
#define FS_BIAS 18432
#define FB_STRIDE 272
#define FBUF (18432 + 128*FB_STRIDE)    // 53248 per buffer
#define FSM_TOT (2*FBUF)                // 106496

__global__ __launch_bounds__(128, 2)
void flash_hmma(const __half* __restrict__ qh, const __half* __restrict__ kh,
                const __half* __restrict__ vh, __half* __restrict__ oh)
{
    extern __shared__ __align__(16) char sm[];
    uint32_t sb = smem_u32(sm);
    int tid = threadIdx.x;
    int w = tid >> 5, lane = tid & 31;
    int gid = lane >> 2, tig = lane & 3;
    int sub = lane >> 3, rin = lane & 7;
    int bh = blockIdx.y;
    int b = bh >> 3, h = bh & 7;
    int i0 = blockIdx.x * 128;

    // ---- stage Q tile (128 rows) into FS_BIAS area of buf0, extract frags ----
    const __half* qhp = qh + ((size_t)(b*TT + i0)) * CC + h * DD;
    #pragma unroll
    for (int u = 0; u < 8; u++) {
        int f = u * 128 + tid;             // 0..1023
        int row = f >> 3, seg = f & 7;
        *(float4*)(sm + FS_BIAS + row*FT_STRIDE + seg*16) =
            *(const float4*)(qhp + (size_t)row*CC + seg*8);
    }
    __syncthreads();
    uint32_t qf[2][4][4];                   // [m-tile][kb][regs]
    #pragma unroll
    for (int am = 0; am < 2; am++) {
        uint32_t qa = sb + FS_BIAS +
            (uint32_t)((w*32 + am*16 + (sub & 1)*8 + rin) * FT_STRIDE + (sub >> 1)*16);
        #pragma unroll
        for (int kb = 0; kb < 4; kb++)
            LDSM_X4(qf[am][kb][0], qf[am][kb][1], qf[am][kb][2], qf[am][kb][3], qa + kb*32);
    }
    __syncthreads();

    float accO[2][8][4];
    #pragma unroll
    for (int am = 0; am < 2; am++)
        #pragma unroll
        for (int nb = 0; nb < 8; nb++)
            #pragma unroll
            for (int c = 0; c < 4; c++) accO[am][nb][c] = 0.f;
    float mrow[2][2], lrow[2][2];
    #pragma unroll
    for (int am = 0; am < 2; am++) {
        mrow[am][0] = -3.0e38f; mrow[am][1] = -3.0e38f;
        lrow[am][0] = 0.f;      lrow[am][1] = 0.f;
    }

    const __half* khp = kh + ((size_t)(b*TT)) * CC + h * DD;
    const __half* vhp = vh + ((size_t)(b*TT)) * CC + h * DD;
    const float* bbase = g_biasT + ((size_t)bh * TT + i0) * TT;

    auto issue_tile = [&](int jt, uint32_t bufo) {
        int j0 = jt * 64;
        #pragma unroll
        for (int u = 0; u < 4; u++) {
            int f = u * 128 + tid;
            int row = f >> 3, seg = f & 7;
            size_t g = (size_t)(j0 + row) * CC + seg * 8;
            uint32_t so = sb + bufo + (uint32_t)(row*FT_STRIDE + seg*16);
            CP_ASYNC16(so + FS_K, khp + g);
            CP_ASYNC16(so + FS_V, vhp + g);
        }
        #pragma unroll
        for (int u = 0; u < 16; u++) {
            int f = u * 128 + tid;          // 0..2047 (128 rows x 16 segs)
            int row = f >> 4, seg = f & 15;
            CP_ASYNC16(sb + bufo + FS_BIAS + (uint32_t)(row*FB_STRIDE + seg*16),
                       bbase + (size_t)row*TT + j0 + seg*4);
        }
    };

    uint32_t kfo = (uint32_t)(((sub >> 1)*8 + rin) * FT_STRIDE + (sub & 1)*16);
    uint32_t vfo = (uint32_t)(((sub & 1)*8 + rin) * FT_STRIDE + (sub >> 1)*16);

    issue_tile(0, 0); CP_COMMIT();
    issue_tile(1, FBUF); CP_COMMIT();

    for (int jt = 0; jt < 16; jt++) {
        uint32_t bufo = (uint32_t)(jt & 1) * FBUF;
        CP_WAIT1();
        __syncthreads();

        // ---- S = Q K^T + bias ----
        float s[2][8][4];
        #pragma unroll
        for (int am = 0; am < 2; am++) {
            int brow = w*32 + am*16 + gid;
            #pragma unroll
            for (int nb = 0; nb < 8; nb++) {
                int bcol = (nb*8 + tig*2) * 4;
                float2 b0 = *(const float2*)(sm + bufo + FS_BIAS + brow*FB_STRIDE + bcol);
                float2 b1 = *(const float2*)(sm + bufo + FS_BIAS + (brow+8)*FB_STRIDE + bcol);
                s[am][nb][0] = b0.x; s[am][nb][1] = b0.y;
                s[am][nb][2] = b1.x; s[am][nb][3] = b1.y;
            }
        }
        #pragma unroll
        for (int kb = 0; kb < 4; kb++) {
            uint32_t kf[8][2];
            #pragma unroll
            for (int nb2 = 0; nb2 < 4; nb2++) {
                uint32_t ka = sb + bufo + FS_K + kfo + (uint32_t)(nb2*16*FT_STRIDE + kb*32);
                LDSM_X4(kf[2*nb2][0], kf[2*nb2][1], kf[2*nb2+1][0], kf[2*nb2+1][1], ka);
            }
            #pragma unroll
            for (int am = 0; am < 2; am++)
                #pragma unroll
                for (int nb = 0; nb < 8; nb++)
                    MMA_F16(s[am][nb], qf[am][kb], kf[nb]);
        }

        // ---- online softmax (per m-tile) ----
        #pragma unroll
        for (int am = 0; am < 2; am++) {
            float mt0 = s[am][0][0], mt1 = s[am][0][2];
            #pragma unroll
            for (int nb = 0; nb < 8; nb++) {
                mt0 = fmaxf(mt0, fmaxf(s[am][nb][0], s[am][nb][1]));
                mt1 = fmaxf(mt1, fmaxf(s[am][nb][2], s[am][nb][3]));
            }
            mt0 = fmaxf(mt0, __shfl_xor_sync(0xffffffffu, mt0, 1));
            mt0 = fmaxf(mt0, __shfl_xor_sync(0xffffffffu, mt0, 2));
            mt1 = fmaxf(mt1, __shfl_xor_sync(0xffffffffu, mt1, 1));
            mt1 = fmaxf(mt1, __shfl_xor_sync(0xffffffffu, mt1, 2));
            float mn0 = fmaxf(mrow[am][0], mt0), mn1 = fmaxf(mrow[am][1], mt1);
            float c0 = fexp(mrow[am][0] - mn0), c1 = fexp(mrow[am][1] - mn1);
            lrow[am][0] *= c0; lrow[am][1] *= c1;
            #pragma unroll
            for (int nb = 0; nb < 8; nb++) {
                accO[am][nb][0] *= c0; accO[am][nb][1] *= c0;
                accO[am][nb][2] *= c1; accO[am][nb][3] *= c1;
            }
            #pragma unroll
            for (int nb = 0; nb < 8; nb++) {
                s[am][nb][0] = fexp(s[am][nb][0] - mn0);
                s[am][nb][1] = fexp(s[am][nb][1] - mn0);
                s[am][nb][2] = fexp(s[am][nb][2] - mn1);
                s[am][nb][3] = fexp(s[am][nb][3] - mn1);
                lrow[am][0] += s[am][nb][0] + s[am][nb][1];
                lrow[am][1] += s[am][nb][2] + s[am][nb][3];
            }
            mrow[am][0] = mn0; mrow[am][1] = mn1;
        }

        // ---- O += P V ----
        #pragma unroll
        for (int kb = 0; kb < 4; kb++) {
            uint32_t ph[2][4];
            #pragma unroll
            for (int am = 0; am < 2; am++) {
                int ne = 2*kb, no = 2*kb + 1;
                __half2 H;
                H = __floats2half2_rn(s[am][ne][0], s[am][ne][1]); ph[am][0] = *reinterpret_cast<uint32_t*>(&H);
                H = __floats2half2_rn(s[am][ne][2], s[am][ne][3]); ph[am][1] = *reinterpret_cast<uint32_t*>(&H);
                H = __floats2half2_rn(s[am][no][0], s[am][no][1]); ph[am][2] = *reinterpret_cast<uint32_t*>(&H);
                H = __floats2half2_rn(s[am][no][2], s[am][no][3]); ph[am][3] = *reinterpret_cast<uint32_t*>(&H);
            }
            uint32_t vf[8][2];
            #pragma unroll
            for (int db2 = 0; db2 < 4; db2++) {
                uint32_t va = sb + bufo + FS_V + vfo + (uint32_t)(kb*16*FT_STRIDE + db2*32);
                LDSM_X4_T(vf[2*db2][0], vf[2*db2][1], vf[2*db2+1][0], vf[2*db2+1][1], va);
            }
            #pragma unroll
            for (int am = 0; am < 2; am++)
                #pragma unroll
                for (int db = 0; db < 8; db++)
                    MMA_F16(accO[am][db], ph[am], vf[db]);
        }

        __syncthreads();
        if (jt + 2 < 16) issue_tile(jt + 2, bufo);
        CP_COMMIT();
    }

    // ---- finalize ----
    #pragma unroll
    for (int am = 0; am < 2; am++) {
        lrow[am][0] += __shfl_xor_sync(0xffffffffu, lrow[am][0], 1);
        lrow[am][0] += __shfl_xor_sync(0xffffffffu, lrow[am][0], 2);
        lrow[am][1] += __shfl_xor_sync(0xffffffffu, lrow[am][1], 1);
        lrow[am][1] += __shfl_xor_sync(0xffffffffu, lrow[am][1], 2);
        float inv0 = 1.f / lrow[am][0], inv1 = 1.f / lrow[am][1];

        size_t r0 = (size_t)(b*TT + i0 + w*32 + am*16 + gid) * CC + h * DD;
        size_t r1 = r0 + 8 * CC;
        #pragma unroll
        for (int nb = 0; nb < 8; nb++) {
            int col = nb*8 + tig*2;
            *(__half2*)(oh + r0 + col) = __floats2half2_rn(accO[am][nb][0]*inv0, accO[am][nb][1]*inv0);
            *(__half2*)(oh + r1 + col) = __floats2half2_rn(accO[am][nb][2]*inv1, accO[am][nb][3]*inv1);
        }
    }
}

// ---------------- launch ----------------
extern "C" void kernel_launch(void* const* d_in, const int* in_sizes, int n_in,
                              void* d_out, int out_size)
{
    const float* x      = (const float*)d_in[0];
    const float* pair   = (const float*)d_in[1];
    const void*  mask   = d_in[2];
    const float* norm_w = (const float*)d_in[3];
    const float* norm_b = (const float*)d_in[4];
    const float* qkv_w  = (const float*)d_in[5];
    const float* qkv_b  = (const float*)d_in[6];
    const float* qln_w  = (const float*)d_in[7];
    const float* qln_b  = (const float*)d_in[8];
    const float* kln_w  = (const float*)d_in[9];
    const float* kln_b  = (const float*)d_in[10];
    const float* proj_w = (const float*)d_in[11];
    const float* proj_b = (const float*)d_in[12];
    float* out = (float*)d_out;

    float *qkvp;
    __half *ah, *wh, *qh, *kh, *vh;
    cudaGetSymbolAddress((void**)&qkvp, g_qkv);
    cudaGetSymbolAddress((void**)&ah, g_ah);
    cudaGetSymbolAddress((void**)&wh, g_wh);
    cudaGetSymbolAddress((void**)&qh, g_qh);
    cudaGetSymbolAddress((void**)&kh, g_kh);
    cudaGetSymbolAddress((void**)&vh, g_vh);

    cudaFuncSetAttribute(flash_hmma, cudaFuncAttributeMaxDynamicSharedMemorySize, FSM_TOT);
    cudaFuncSetAttribute(gemm_tc16, cudaFuncAttributeMaxDynamicSharedMemorySize, GSMEM);

    // 0. mask dtype detection (front of stream)
    detect_mask_kind<<<1, 256>>>(mask);
    // 1. pre-norm + fp16 convert
    ln_h_kernel<<<NROWS, 128>>>(x, norm_w, norm_b, ah);
    // 2. convert qkv weights + QKV GEMM (HMMA fp16)
    cvt_kernel<<<(C3*CC/4 + 255)/256, 256>>>(qkv_w, wh, C3*CC/4);
    gemm_tc16<<<dim3(C3/128, NROWS/128), 128, GSMEM>>>(ah, wh, qkv_b, qkvp, C3, CC);
    // 3. q/k LN + scale fold + fp16 converts (fused)
    qkv_post<<<NROWS, 128>>>(qkvp, qln_w, qln_b, kln_w, kln_b);
    // 4. pair transpose with mask fold
    bias_transpose_kernel<<<dim3(TT/128, TT, BB), 256>>>(pair, mask);
    // 5. fp16 flash attention (128-row CTAs) -> fp16 out (reuse ah)
    flash_hmma<<<dim3(TT/128, BB*HH), 128, FSM_TOT>>>(qh, kh, vh, ah);
    // 6. output projection (HMMA fp16)
    cvt_kernel<<<(CC*CC/4 + 255)/256, 256>>>(proj_w, wh, CC*CC/4);
    gemm_tc16<<<dim3(CC/128, NROWS/128), 128, GSMEM>>>(ah, wh, proj_b, out, CC, CC);
}

// round 11
// speedup vs baseline: 1.5906x; 1.0340x over previous
#include <cuda_runtime.h>
#include <cuda_fp16.h>
#include <cstdint>

// Problem constants
#define BB 4
#define TT 1024
#define CC 512
#define HH 8
#define DD 64
#define NROWS (BB*TT)          // 4096
#define C3 (3*CC)              // 1536
#define NEGF (-3.402823466e38f)

// -------- scratch (static device globals; allocation-free) --------
__device__ float g_qkv[(size_t)NROWS*C3];         // 24 MB
__device__ float g_biasT[(size_t)BB*HH*TT*TT];    // 128 MB
__device__ int   g_mask_kind;
__device__ __half g_ah[(size_t)NROWS*CC];         // GEMM A / attn out (fp16)
__device__ __half g_wh[(size_t)C3*CC];            // qkv weights fp16
__device__ __half g_wp[(size_t)CC*CC];            // proj weights fp16 (separate: overlap)
__device__ __half g_qh[(size_t)NROWS*CC];
__device__ __half g_kh[(size_t)NROWS*CC];
__device__ __half g_vh[(size_t)NROWS*CC];

// -------- host-side stream/event resources (created at program start) --------
struct HxStreams {
    cudaStream_t s2;
    cudaEvent_t evFork, evJoin;
    HxStreams() {
        cudaStreamCreate(&s2);
        cudaEventCreateWithFlags(&evFork, cudaEventDisableTiming);
        cudaEventCreateWithFlags(&evJoin, cudaEventDisableTiming);
    }
};
static HxStreams g_hx;

// ================ generic-PTX helpers ================
__device__ __forceinline__ uint32_t smem_u32(const void* p) {
    uint32_t a;
    asm("{ .reg .u64 t; cvta.to.shared.u64 t, %1; cvt.u32.u64 %0, t; }"
        : "=r"(a) : "l"(p));
    return a;
}
#define LDSM_X4(r0, r1, r2, r3, addr) \
    asm volatile("ldmatrix.sync.aligned.m8n8.x4.shared.b16 {%0,%1,%2,%3}, [%4];" \
        : "=r"(r0), "=r"(r1), "=r"(r2), "=r"(r3) : "r"(addr))
#define LDSM_X4_T(r0, r1, r2, r3, addr) \
    asm volatile("ldmatrix.sync.aligned.m8n8.x4.trans.shared.b16 {%0,%1,%2,%3}, [%4];" \
        : "=r"(r0), "=r"(r1), "=r"(r2), "=r"(r3) : "r"(addr))
#define MMA_F16(d, a, b) \
    asm volatile("mma.sync.aligned.m16n8k16.row.col.f32.f16.f16.f32 " \
        "{%0,%1,%2,%3}, {%4,%5,%6,%7}, {%8,%9}, {%0,%1,%2,%3};" \
        : "+f"((d)[0]), "+f"((d)[1]), "+f"((d)[2]), "+f"((d)[3]) \
        : "r"((a)[0]), "r"((a)[1]), "r"((a)[2]), "r"((a)[3]), \
          "r"((b)[0]), "r"((b)[1]))
#define CP_ASYNC16(saddr, gptr) \
    asm volatile("cp.async.cg.shared.global [%0], [%1], 16;" \
        :: "r"(saddr), "l"(gptr))
#define CP_COMMIT() asm volatile("cp.async.commit_group;" ::: "memory")
#define CP_WAIT1()  asm volatile("cp.async.wait_group 1;" ::: "memory")

// fast exp on FMA pipe
__device__ __forceinline__ float fexp(float x) {
    float t = fmaxf(x * 1.4426950408889634f, -126.f);
    float fi = floorf(t);
    float f = t - fi;
    float p = 1.5403530393381609e-4f;
    p = fmaf(p, f, 1.3333558146428443e-3f);
    p = fmaf(p, f, 9.6181291976036826e-3f);
    p = fmaf(p, f, 5.5504108664821580e-2f);
    p = fmaf(p, f, 2.4022650695910071e-1f);
    p = fmaf(p, f, 6.9314718055994531e-1f);
    p = fmaf(p, f, 1.0f);
    int ii = (int)fi;
    return p * __int_as_float((ii + 127) << 23);
}

// ================ LayerNorm core ================
__device__ __forceinline__ float warp_sum(float v) {
    #pragma unroll
    for (int o = 16; o; o >>= 1) v += __shfl_xor_sync(0xffffffffu, v, o);
    return v;
}

__device__ __forceinline__ void ln_core(float4& v, const float* w, const float* b,
                                        int t, float4& o)
{
    float s  = v.x + v.y + v.z + v.w;
    float sq = v.x*v.x + v.y*v.y + v.z*v.z + v.w*v.w;
    s = warp_sum(s); sq = warp_sum(sq);
    __shared__ float sh[8];
    int wid = t >> 5, lid = t & 31;
    if (lid == 0) { sh[wid] = s; sh[4 + wid] = sq; }
    __syncthreads();
    float ts = sh[0] + sh[1] + sh[2] + sh[3];
    float tq = sh[4] + sh[5] + sh[6] + sh[7];
    float mean = ts * (1.f / CC);
    float var  = tq * (1.f / CC) - mean * mean;
    float rstd = rsqrtf(var + 1e-5f);
    float4 wv = *(const float4*)(w + t * 4);
    float4 bv = *(const float4*)(b + t * 4);
    o.x = (v.x - mean) * rstd * wv.x + bv.x;
    o.y = (v.y - mean) * rstd * wv.y + bv.y;
    o.z = (v.z - mean) * rstd * wv.z + bv.z;
    o.w = (v.w - mean) * rstd * wv.w + bv.w;
}

__device__ __forceinline__ void h_store4(float4 o, __half* dst, size_t base)
{
    *(__half2*)(dst + base)     = __floats2half2_rn(o.x, o.y);
    *(__half2*)(dst + base + 2) = __floats2half2_rn(o.z, o.w);
}

__global__ void ln_h_kernel(const float* src, const float* __restrict__ w,
                            const float* __restrict__ b, __half* dst)
{
    int row = blockIdx.x, t = threadIdx.x;
    float4 v = *(const float4*)(src + (size_t)row * CC + t * 4);
    float4 o;
    ln_core(v, w, b, t, o);
    h_store4(o, dst, (size_t)row * CC + t * 4);
}

__global__ void qkv_post(const float* __restrict__ qkv,
                         const float* __restrict__ qw, const float* __restrict__ qb,
                         const float* __restrict__ kw, const float* __restrict__ kb)
{
    int row = blockIdx.x, t = threadIdx.x;
    const float* rp = qkv + (size_t)row * C3;
    size_t base = (size_t)row * CC + t * 4;
    float4 v = *(const float4*)(rp + t * 4);
    float4 o;
    ln_core(v, qw, qb, t, o);
    o.x *= 0.125f; o.y *= 0.125f; o.z *= 0.125f; o.w *= 0.125f;
    h_store4(o, g_qh, base);
    __syncthreads();
    v = *(const float4*)(rp + CC + t * 4);
    ln_core(v, kw, kb, t, o);
    h_store4(o, g_kh, base);
    v = *(const float4*)(rp + 2 * CC + t * 4);
    h_store4(v, g_vh, base);
}

__global__ void cvt_kernel(const float* __restrict__ src, __half* dst, int n4)
{
    int i = blockIdx.x * blockDim.x + threadIdx.x;
    if (i >= n4) return;
    float4 v = ((const float4*)src)[i];
    h_store4(v, dst, (size_t)i * 4);
}

// ================ HMMA fp16 GEMM: 4 warps, warp tile 64x64 ================
#define GT_STRIDE 80
#define GT_TILE   (128*GT_STRIDE)       // 10240
#define G_A 0
#define G_B GT_TILE
#define GBUF  (2*GT_TILE)               // 20480 per buffer
#define GSMEM (2*GBUF)                  // 40960

__global__ __launch_bounds__(128, 2)
void gemm_tc16(const __half* __restrict__ A, const __half* __restrict__ B,
               const float* __restrict__ bias, float* __restrict__ C,
               int N, int K)
{
    extern __shared__ __align__(16) char smem[];
    uint32_t sb = smem_u32(smem);

    int tid = threadIdx.x;
    int wid = tid >> 5, lane = tid & 31;
    int wm = wid >> 1, wn = wid & 1;       // 2x2 warp grid, warp tile 64x64
    int gid = lane >> 2, tig = lane & 3;
    int m0 = blockIdx.y * 128, n0 = blockIdx.x * 128;

    float acc[4][8][4];
    #pragma unroll
    for (int i = 0; i < 4; i++)
        #pragma unroll
        for (int j = 0; j < 8; j++)
            #pragma unroll
            for (int c = 0; c < 4; c++) acc[i][j][c] = 0.f;

    int lrow = tid >> 2, lseg = tid & 3;   // base row 0..31, seg 0..3

    auto issue = [&](int kc0, uint32_t bufo) {
        #pragma unroll
        for (int i = 0; i < 4; i++) {
            int row = lrow + i * 32;
            size_t ga = (size_t)(m0 + row) * K + kc0 + lseg * 8;
            size_t gb = (size_t)(n0 + row) * K + kc0 + lseg * 8;
            uint32_t so = sb + bufo + (uint32_t)(row * GT_STRIDE + lseg * 16);
            CP_ASYNC16(so + G_A, A + ga);
            CP_ASYNC16(so + G_B, B + gb);
        }
    };

    int sub = lane >> 3, rin = lane & 7;
    uint32_t aoff = (uint32_t)((wm*64 + (sub & 1)*8 + rin) * GT_STRIDE + (sub >> 1) * 16);
    uint32_t boff = (uint32_t)((wn*64 + (sub >> 1)*8 + rin) * GT_STRIDE + (sub & 1) * 16);

    int nch = K >> 5;
    issue(0, 0); CP_COMMIT();
    issue(32, GBUF); CP_COMMIT();

    for (int ch = 0; ch < nch; ch++) {
        uint32_t bufo = (uint32_t)(ch & 1) * GBUF;
        CP_WAIT1();
        __syncthreads();

        #pragma unroll
        for (int ks = 0; ks < 2; ks++) {
            uint32_t fA[4][4];
            #pragma unroll
            for (int am = 0; am < 4; am++) {
                uint32_t ad = sb + bufo + G_A + aoff + am * (16 * GT_STRIDE) + ks * 32;
                LDSM_X4(fA[am][0], fA[am][1], fA[am][2], fA[am][3], ad);
            }
            uint32_t fB[8][2];
            #pragma unroll
            for (int bg = 0; bg < 4; bg++) {
                uint32_t bd = sb + bufo + G_B + boff + bg * (16 * GT_STRIDE) + ks * 32;
                LDSM_X4(fB[2*bg][0], fB[2*bg][1], fB[2*bg+1][0], fB[2*bg+1][1], bd);
            }
            // product-major: each accumulator touched once per 32-MMA sweep
            #pragma unroll
            for (int am = 0; am < 4; am++)
                #pragma unroll
                for (int nb = 0; nb < 8; nb++)
                    MMA_F16(acc[am][nb], fA[am], fB[nb]);
        }
        __syncthreads();
        if (ch + 2 < nch) issue((ch + 2) << 5, bufo);
        CP_COMMIT();
    }

    #pragma unroll
    for (int am = 0; am < 4; am++) {
        int row = m0 + wm*64 + am*16 + gid;
        #pragma unroll
        for (int nb = 0; nb < 8; nb++) {
            int col = n0 + wn*64 + nb*8 + tig*2;
            float2 bv = *(const float2*)(bias + col);
            float2 o0 = { acc[am][nb][0] + bv.x, acc[am][nb][1] + bv.y };
            float2 o1 = { acc[am][nb][2] + bv.x, acc[am][nb][3] + bv.y };
            *(float2*)(C + (size_t)row * N + col)       = o0;
            *(float2*)(C + (size_t)(row + 8) * N + col) = o1;
        }
    }
}

// ---------------- mask dtype detection ----------------
__global__ void detect_mask_kind(const void* mask)
{
    __shared__ int s_int, s_float;
    if (threadIdx.x == 0) { s_int = 1; s_float = 1; }
    __syncthreads();
    const unsigned int* w = (const unsigned int*)mask;
    int ok_i = 1, ok_f = 1;
    for (int i = threadIdx.x; i < 1024; i += blockDim.x) {
        unsigned int v = w[i];
        if (v > 1u) ok_i = 0;
        if (v != 0u && v != 0x3F800000u) ok_f = 0;
    }
    atomicAnd(&s_int, ok_i);
    atomicAnd(&s_float, ok_f);
    __syncthreads();
    if (threadIdx.x == 0) g_mask_kind = s_int ? 0 : (s_float ? 1 : 2);
}

// ---------------- pair [B,T,T,H] -> biasT [B,H,T,T], folding mask ----------------
__global__ void bias_transpose_kernel(const float* __restrict__ pair,
                                      const void* __restrict__ mask)
{
    __shared__ float sp[128][9];
    __shared__ float addm[128];
    int b = blockIdx.z, i = blockIdx.y, j0 = blockIdx.x * 128;
    int t = threadIdx.x;

    const float* src = pair + (((size_t)(b * TT + i) * TT) + j0) * HH;
    {
        int f = t * 4;
        int tj = f >> 3;
        int h0 = f & 7;
        float4 v = *(const float4*)(src + f);
        sp[tj][h0]   = v.x; sp[tj][h0+1] = v.y;
        sp[tj][h0+2] = v.z; sp[tj][h0+3] = v.w;
    }
    if (t < 128) {
        size_t mi = ((size_t)(b * TT + i)) * TT + j0 + t;
        int kind = g_mask_kind;
        bool mv;
        if (kind == 0)      mv = ((const int*)mask)[mi] != 0;
        else if (kind == 1) mv = ((const float*)mask)[mi] != 0.f;
        else                mv = ((const unsigned char*)mask)[mi] != 0;
        addm[t] = mv ? 0.f : NEGF;
    }
    __syncthreads();
    #pragma unroll
    for (int u = 0; u < 4; u++) {
        int f = t + 256 * u;
        int h = f >> 7;
        int tj = f & 127;
        g_biasT[(((size_t)(b * HH + h) * TT + i) * TT) + j0 + tj] = sp[tj][h] + addm[tj];
    }
}

// ================ HMMA fp16 flash attention: 128 Q rows, warp=32 rows ================
#define FT_STRIDE 144
#define FS_K 0
#define FS_V 9216
#define FS_BIAS 18432
#define FB_STRIDE 272
#define FBUF (18432 + 128*FB_STRIDE)    // 53248 per buffer
#define FSM_TOT (2*FBUF)                // 106496

__global__ __launch_bounds__(128, 2)
void flash_hmma(const __half* __restrict__ qh, const __half* __restrict__ kh,
                const __half* __restrict__ vh, __half* __restrict__ oh)
{
    extern __shared__ __align__(16) char sm[];
    uint32_t sb = smem_u32(sm);
    int tid = threadIdx.x;
    int w = tid >> 5, lane = tid & 31;
    int gid = lane >> 2, tig = lane & 3;
    int sub = lane >> 3, rin = lane & 7;
    int bh = blockIdx.y;
    int b = bh >> 3, h = bh & 7;
    int i0 = blockIdx.x * 128;

    // ---- stage Q tile (128 rows) into FS_BIAS area of buf0, extract frags ----
    const __half* qhp = qh + ((size_t)(b*TT + i0)) * CC + h * DD;
    #pragma unroll
    for (int u = 0; u < 8; u++) {
        int f = u * 128 + tid;             // 0..1023
        int row = f >> 3, seg = f & 7;
        *(float4*)(sm + FS_BIAS + row*FT_STRIDE + seg*16) =
            *(const float4*)(qhp + (size_t)row*CC + seg*8);
    }
    __syncthreads();
    uint32_t qf[2][4][4];                   // [m-tile][kb][regs]
    #pragma unroll
    for (int am = 0; am < 2; am++) {
        uint32_t qa = sb + FS_BIAS +
            (uint32_t)((w*32 + am*16 + (sub & 1)*8 + rin) * FT_STRIDE + (sub >> 1)*16);
        #pragma unroll
        for (int kb = 0; kb < 4; kb++)
            LDSM_X4(qf[am][kb][0], qf[am][kb][1], qf[am][kb][2], qf[am][kb][3], qa + kb*32);
    }
    __syncthreads();

    float accO[2][8][4];
    #pragma unroll
    for (int am = 0; am < 2; am++)
        #pragma unroll
        for (int nb = 0; nb < 8; nb++)
            #pragma unroll
            for (int c = 0; c < 4; c++) accO[am][nb][c] = 0.f;
    float mrow[2][2], lrow[2][2];
    #pragma unroll
    for (int am = 0; am < 2; am++) {
        mrow[am][0] = -3.0e38f; mrow[am][1] = -3.0e38f;
        lrow[am][0] = 0.f;      lrow[am][1] = 0.f;
    }

    const __half* khp = kh + ((size_t)(b*TT)) * CC + h * DD;
    const __half* vhp = vh + ((size_t)(b*TT)) * CC + h * DD;
    const float* bbase = g_biasT + ((size_t)bh * TT + i0) * TT;

    auto issue_tile = [&](int jt, uint32_t bufo) {
        int j0 = jt * 64;
        #pragma unroll
        for (int u = 0; u < 4; u++) {
            int f = u * 128 + tid;
            int row = f >> 3, seg = f & 7;
            size_t g = (size_t)(j0 + row) * CC + seg * 8;
            uint32_t so = sb + bufo + (uint32_t)(row*FT_STRIDE + seg*16);
            CP_ASYNC16(so + FS_K, khp + g);
            CP_ASYNC16(so + FS_V, vhp + g);
        }
        #pragma unroll
        for (int u = 0; u < 16; u++) {
            int f = u * 128 + tid;          // 0..2047 (128 rows x 16 segs)
            int row = f >> 4, seg = f & 15;
            CP_ASYNC16(sb + bufo + FS_BIAS + (uint32_t)(row*FB_STRIDE + seg*16),
                       bbase + (size_t)row*TT + j0 + seg*4);
        }
    };

    uint32_t kfo = (uint32_t)(((sub >> 1)*8 + rin) * FT_STRIDE + (sub & 1)*16);
    uint32_t vfo = (uint32_t)(((sub & 1)*8 + rin) * FT_STRIDE + (sub >> 1)*16);

    issue_tile(0, 0); CP_COMMIT();
    issue_tile(1, FBUF); CP_COMMIT();

    for (int jt = 0; jt < 16; jt++) {
        uint32_t bufo = (uint32_t)(jt & 1) * FBUF;
        CP_WAIT1();
        __syncthreads();

        // ---- S = Q K^T + bias ----
        float s[2][8][4];
        #pragma unroll
        for (int am = 0; am < 2; am++) {
            int brow = w*32 + am*16 + gid;
            #pragma unroll
            for (int nb = 0; nb < 8; nb++) {
                int bcol = (nb*8 + tig*2) * 4;
                float2 b0 = *(const float2*)(sm + bufo + FS_BIAS + brow*FB_STRIDE + bcol);
                float2 b1 = *(const float2*)(sm + bufo + FS_BIAS + (brow+8)*FB_STRIDE + bcol);
                s[am][nb][0] = b0.x; s[am][nb][1] = b0.y;
                s[am][nb][2] = b1.x; s[am][nb][3] = b1.y;
            }
        }
        #pragma unroll
        for (int kb = 0; kb < 4; kb++) {
            uint32_t kf[8][2];
            #pragma unroll
            for (int nb2 = 0; nb2 < 4; nb2++) {
                uint32_t ka = sb + bufo + FS_K + kfo + (uint32_t)(nb2*16*FT_STRIDE + kb*32);
                LDSM_X4(kf[2*nb2][0], kf[2*nb2][1], kf[2*nb2+1][0], kf[2*nb2+1][1], ka);
            }
            #pragma unroll
            for (int am = 0; am < 2; am++)
                #pragma unroll
                for (int nb = 0; nb < 8; nb++)
                    MMA_F16(s[am][nb], qf[am][kb], kf[nb]);
        }

        // ---- online softmax (per m-tile) ----
        #pragma unroll
        for (int am = 0; am < 2; am++) {
            float mt0 = s[am][0][0], mt1 = s[am][0][2];
            #pragma unroll
            for (int nb = 0; nb < 8; nb++) {
                mt0 = fmaxf(mt0, fmaxf(s[am][nb][0], s[am][nb][1]));
                mt1 = fmaxf(mt1, fmaxf(s[am][nb][2], s[am][nb][3]));
            }
            mt0 = fmaxf(mt0, __shfl_xor_sync(0xffffffffu, mt0, 1));
            mt0 = fmaxf(mt0, __shfl_xor_sync(0xffffffffu, mt0, 2));
            mt1 = fmaxf(mt1, __shfl_xor_sync(0xffffffffu, mt1, 1));
            mt1 = fmaxf(mt1, __shfl_xor_sync(0xffffffffu, mt1, 2));
            float mn0 = fmaxf(mrow[am][0], mt0), mn1 = fmaxf(mrow[am][1], mt1);
            float c0 = fexp(mrow[am][0] - mn0), c1 = fexp(mrow[am][1] - mn1);
            lrow[am][0] *= c0; lrow[am][1] *= c1;
            #pragma unroll
            for (int nb = 0; nb < 8; nb++) {
                accO[am][nb][0] *= c0; accO[am][nb][1] *= c0;
                accO[am][nb][2] *= c1; accO[am][nb][3] *= c1;
            }
            #pragma unroll
            for (int nb = 0; nb < 8; nb++) {
                s[am][nb][0] = fexp(s[am][nb][0] - mn0);
                s[am][nb][1] = fexp(s[am][nb][1] - mn0);
                s[am][nb][2] = fexp(s[am][nb][2] - mn1);
                s[am][nb][3] = fexp(s[am][nb][3] - mn1);
                lrow[am][0] += s[am][nb][0] + s[am][nb][1];
                lrow[am][1] += s[am][nb][2] + s[am][nb][3];
            }
            mrow[am][0] = mn0; mrow[am][1] = mn1;
        }

        // ---- O += P V ----
        #pragma unroll
        for (int kb = 0; kb < 4; kb++) {
            uint32_t ph[2][4];
            #pragma unroll
            for (int am = 0; am < 2; am++) {
                int ne = 2*kb, no = 2*kb + 1;
                __half2 H;
                H = __floats2half2_rn(s[am][ne][0], s[am][ne][1]); ph[am][0] = *reinterpret_cast<uint32_t*>(&H);
                H = __floats2half2_rn(s[am][ne][2], s[am][ne][3]); ph[am][1] = *reinterpret_cast<uint32_t*>(&H);
                H = __floats2half2_rn(s[am][no][0], s[am][no][1]); ph[am][2] = *reinterpret_cast<uint32_t*>(&H);
                H = __floats2half2_rn(s[am][no][2], s[am][no][3]); ph[am][3] = *reinterpret_cast<uint32_t*>(&H);
            }
            uint32_t vf[8][2];
            #pragma unroll
            for (int db2 = 0; db2 < 4; db2++) {
                uint32_t va = sb + bufo + FS_V + vfo + (uint32_t)(kb*16*FT_STRIDE + db2*32);
                LDSM_X4_T(vf[2*db2][0], vf[2*db2][1], vf[2*db2+1][0], vf[2*db2+1][1], va);
            }
            #pragma unroll
            for (int am = 0; am < 2; am++)
                #pragma unroll
                for (int db = 0; db < 8; db++)
                    MMA_F16(accO[am][db], ph[am], vf[db]);
        }

        __syncthreads();
        if (jt + 2 < 16) issue_tile(jt + 2, bufo);
        CP_COMMIT();
    }

    // ---- finalize ----
    #pragma unroll
    for (int am = 0; am < 2; am++) {
        lrow[am][0] += __shfl_xor_sync(0xffffffffu, lrow[am][0], 1);
        lrow[am][0] += __shfl_xor_sync(0xffffffffu, lrow[am][0], 2);
        lrow[am][1] += __shfl_xor_sync(0xffffffffu, lrow[am][1], 1);
        lrow[am][1] += __shfl_xor_sync(0xffffffffu, lrow[am][1], 2);
        float inv0 = 1.f / lrow[am][0], inv1 = 1.f / lrow[am][1];

        size_t r0 = (size_t)(b*TT + i0 + w*32 + am*16 + gid) * CC + h * DD;
        size_t r1 = r0 + 8 * CC;
        #pragma unroll
        for (int nb = 0; nb < 8; nb++) {
            int col = nb*8 + tig*2;
            *(__half2*)(oh + r0 + col) = __floats2half2_rn(accO[am][nb][0]*inv0, accO[am][nb][1]*inv0);
            *(__half2*)(oh + r1 + col) = __floats2half2_rn(accO[am][nb][2]*inv1, accO[am][nb][3]*inv1);
        }
    }
}

// ---------------- launch ----------------
extern "C" void kernel_launch(void* const* d_in, const int* in_sizes, int n_in,
                              void* d_out, int out_size)
{
    const float* x      = (const float*)d_in[0];
    const float* pair   = (const float*)d_in[1];
    const void*  mask   = d_in[2];
    const float* norm_w = (const float*)d_in[3];
    const float* norm_b = (const float*)d_in[4];
    const float* qkv_w  = (const float*)d_in[5];
    const float* qkv_b  = (const float*)d_in[6];
    const float* qln_w  = (const float*)d_in[7];
    const float* qln_b  = (const float*)d_in[8];
    const float* kln_w  = (const float*)d_in[9];
    const float* kln_b  = (const float*)d_in[10];
    const float* proj_w = (const float*)d_in[11];
    const float* proj_b = (const float*)d_in[12];
    float* out = (float*)d_out;

    float *qkvp;
    __half *ah, *wh, *wp, *qh, *kh, *vh;
    cudaGetSymbolAddress((void**)&qkvp, g_qkv);
    cudaGetSymbolAddress((void**)&ah, g_ah);
    cudaGetSymbolAddress((void**)&wh, g_wh);
    cudaGetSymbolAddress((void**)&wp, g_wp);
    cudaGetSymbolAddress((void**)&qh, g_qh);
    cudaGetSymbolAddress((void**)&kh, g_kh);
    cudaGetSymbolAddress((void**)&vh, g_vh);

    cudaFuncSetAttribute(flash_hmma, cudaFuncAttributeMaxDynamicSharedMemorySize, FSM_TOT);
    cudaFuncSetAttribute(gemm_tc16, cudaFuncAttributeMaxDynamicSharedMemorySize, GSMEM);

    cudaStream_t s0 = 0;             // stream the harness captures (launch stream)
    cudaStream_t s2 = g_hx.s2;

    // ---- fork: branch B (bias path) runs concurrently on s2 ----
    cudaEventRecord(g_hx.evFork, s0);
    cudaStreamWaitEvent(s2, g_hx.evFork, 0);

    // branch B: mask detect + pair transpose + proj weight cvt (independent of QKV path)
    detect_mask_kind<<<1, 256, 0, s2>>>(mask);
    bias_transpose_kernel<<<dim3(TT/128, TT, BB), 256, 0, s2>>>(pair, mask);
    cvt_kernel<<<(CC*CC/4 + 255)/256, 256, 0, s2>>>(proj_w, wp, CC*CC/4);
    cudaEventRecord(g_hx.evJoin, s2);

    // branch A: QKV path on s0
    ln_h_kernel<<<NROWS, 128, 0, s0>>>(x, norm_w, norm_b, ah);
    cvt_kernel<<<(C3*CC/4 + 255)/256, 256, 0, s0>>>(qkv_w, wh, C3*CC/4);
    gemm_tc16<<<dim3(C3/128, NROWS/128), 128, GSMEM, s0>>>(ah, wh, qkv_b, qkvp, C3, CC);
    qkv_post<<<NROWS, 128, 0, s0>>>(qkvp, qln_w, qln_b, kln_w, kln_b);

    // ---- join: flash needs both branches ----
    cudaStreamWaitEvent(s0, g_hx.evJoin, 0);
    flash_hmma<<<dim3(TT/128, BB*HH), 128, FSM_TOT, s0>>>(qh, kh, vh, ah);
    gemm_tc16<<<dim3(CC/128, NROWS/128), 128, GSMEM, s0>>>(ah, wp, proj_b, out, CC, CC);
}

// round 12
// speedup vs baseline: 1.6930x; 1.0644x over previous
#include <cuda_runtime.h>
#include <cuda_fp16.h>
#include <cstdint>

// Problem constants
#define BB 4
#define TT 1024
#define CC 512
#define HH 8
#define DD 64
#define NROWS (BB*TT)          // 4096
#define C3 (3*CC)              // 1536
#define NEGF (-3.402823466e38f)

// -------- scratch (static device globals; allocation-free) --------
__device__ float g_qkv[(size_t)NROWS*C3];         // 24 MB
__device__ float g_maskadd[(size_t)BB*TT*TT];     // 16 MB: 0 or NEGF
__device__ int   g_mask_kind;
__device__ __half g_ah[(size_t)NROWS*CC];         // GEMM A / attn out (fp16)
__device__ __half g_wh[(size_t)C3*CC];            // qkv weights fp16
__device__ __half g_wp[(size_t)CC*CC];            // proj weights fp16
__device__ __half g_qh[(size_t)NROWS*CC];
__device__ __half g_kh[(size_t)NROWS*CC];
__device__ __half g_vh[(size_t)NROWS*CC];

// -------- host-side stream/event resources (created at program start) --------
struct HxStreams {
    cudaStream_t s2;
    cudaEvent_t evFork, evJoin;
    HxStreams() {
        cudaStreamCreate(&s2);
        cudaEventCreateWithFlags(&evFork, cudaEventDisableTiming);
        cudaEventCreateWithFlags(&evJoin, cudaEventDisableTiming);
    }
};
static HxStreams g_hx;

// ================ generic-PTX helpers ================
__device__ __forceinline__ uint32_t smem_u32(const void* p) {
    uint32_t a;
    asm("{ .reg .u64 t; cvta.to.shared.u64 t, %1; cvt.u32.u64 %0, t; }"
        : "=r"(a) : "l"(p));
    return a;
}
#define LDSM_X4(r0, r1, r2, r3, addr) \
    asm volatile("ldmatrix.sync.aligned.m8n8.x4.shared.b16 {%0,%1,%2,%3}, [%4];" \
        : "=r"(r0), "=r"(r1), "=r"(r2), "=r"(r3) : "r"(addr))
#define LDSM_X4_T(r0, r1, r2, r3, addr) \
    asm volatile("ldmatrix.sync.aligned.m8n8.x4.trans.shared.b16 {%0,%1,%2,%3}, [%4];" \
        : "=r"(r0), "=r"(r1), "=r"(r2), "=r"(r3) : "r"(addr))
#define MMA_F16(d, a, b) \
    asm volatile("mma.sync.aligned.m16n8k16.row.col.f32.f16.f16.f32 " \
        "{%0,%1,%2,%3}, {%4,%5,%6,%7}, {%8,%9}, {%0,%1,%2,%3};" \
        : "+f"((d)[0]), "+f"((d)[1]), "+f"((d)[2]), "+f"((d)[3]) \
        : "r"((a)[0]), "r"((a)[1]), "r"((a)[2]), "r"((a)[3]), \
          "r"((b)[0]), "r"((b)[1]))
#define CP_ASYNC16(saddr, gptr) \
    asm volatile("cp.async.cg.shared.global [%0], [%1], 16;" \
        :: "r"(saddr), "l"(gptr))
#define CP_COMMIT() asm volatile("cp.async.commit_group;" ::: "memory")
#define CP_WAIT1()  asm volatile("cp.async.wait_group 1;" ::: "memory")

// fast exp on FMA pipe
__device__ __forceinline__ float fexp(float x) {
    float t = fmaxf(x * 1.4426950408889634f, -126.f);
    float fi = floorf(t);
    float f = t - fi;
    float p = 1.5403530393381609e-4f;
    p = fmaf(p, f, 1.3333558146428443e-3f);
    p = fmaf(p, f, 9.6181291976036826e-3f);
    p = fmaf(p, f, 5.5504108664821580e-2f);
    p = fmaf(p, f, 2.4022650695910071e-1f);
    p = fmaf(p, f, 6.9314718055994531e-1f);
    p = fmaf(p, f, 1.0f);
    int ii = (int)fi;
    return p * __int_as_float((ii + 127) << 23);
}

// ================ LayerNorm core ================
__device__ __forceinline__ float warp_sum(float v) {
    #pragma unroll
    for (int o = 16; o; o >>= 1) v += __shfl_xor_sync(0xffffffffu, v, o);
    return v;
}

__device__ __forceinline__ void ln_core(float4& v, const float* w, const float* b,
                                        int t, float4& o)
{
    float s  = v.x + v.y + v.z + v.w;
    float sq = v.x*v.x + v.y*v.y + v.z*v.z + v.w*v.w;
    s = warp_sum(s); sq = warp_sum(sq);
    __shared__ float sh[8];
    int wid = t >> 5, lid = t & 31;
    if (lid == 0) { sh[wid] = s; sh[4 + wid] = sq; }
    __syncthreads();
    float ts = sh[0] + sh[1] + sh[2] + sh[3];
    float tq = sh[4] + sh[5] + sh[6] + sh[7];
    float mean = ts * (1.f / CC);
    float var  = tq * (1.f / CC) - mean * mean;
    float rstd = rsqrtf(var + 1e-5f);
    float4 wv = *(const float4*)(w + t * 4);
    float4 bv = *(const float4*)(b + t * 4);
    o.x = (v.x - mean) * rstd * wv.x + bv.x;
    o.y = (v.y - mean) * rstd * wv.y + bv.y;
    o.z = (v.z - mean) * rstd * wv.z + bv.z;
    o.w = (v.w - mean) * rstd * wv.w + bv.w;
}

__device__ __forceinline__ void h_store4(float4 o, __half* dst, size_t base)
{
    *(__half2*)(dst + base)     = __floats2half2_rn(o.x, o.y);
    *(__half2*)(dst + base + 2) = __floats2half2_rn(o.z, o.w);
}

__global__ void ln_h_kernel(const float* src, const float* __restrict__ w,
                            const float* __restrict__ b, __half* dst)
{
    int row = blockIdx.x, t = threadIdx.x;
    float4 v = *(const float4*)(src + (size_t)row * CC + t * 4);
    float4 o;
    ln_core(v, w, b, t, o);
    h_store4(o, dst, (size_t)row * CC + t * 4);
}

__global__ void qkv_post(const float* __restrict__ qkv,
                         const float* __restrict__ qw, const float* __restrict__ qb,
                         const float* __restrict__ kw, const float* __restrict__ kb)
{
    int row = blockIdx.x, t = threadIdx.x;
    const float* rp = qkv + (size_t)row * C3;
    size_t base = (size_t)row * CC + t * 4;
    float4 v = *(const float4*)(rp + t * 4);
    float4 o;
    ln_core(v, qw, qb, t, o);
    o.x *= 0.125f; o.y *= 0.125f; o.z *= 0.125f; o.w *= 0.125f;
    h_store4(o, g_qh, base);
    __syncthreads();
    v = *(const float4*)(rp + CC + t * 4);
    ln_core(v, kw, kb, t, o);
    h_store4(o, g_kh, base);
    v = *(const float4*)(rp + 2 * CC + t * 4);
    h_store4(v, g_vh, base);
}

__global__ void cvt_kernel(const float* __restrict__ src, __half* dst, int n4)
{
    int i = blockIdx.x * blockDim.x + threadIdx.x;
    if (i >= n4) return;
    float4 v = ((const float4*)src)[i];
    h_store4(v, dst, (size_t)i * 4);
}

// ================ HMMA fp16 GEMM: 4 warps, warp tile 64x64 ================
#define GT_STRIDE 80
#define GT_TILE   (128*GT_STRIDE)       // 10240
#define G_A 0
#define G_B GT_TILE
#define GBUF  (2*GT_TILE)               // 20480 per buffer
#define GSMEM (2*GBUF)                  // 40960

__global__ __launch_bounds__(128, 2)
void gemm_tc16(const __half* __restrict__ A, const __half* __restrict__ B,
               const float* __restrict__ bias, float* __restrict__ C,
               int N, int K)
{
    extern __shared__ __align__(16) char smem[];
    uint32_t sb = smem_u32(smem);

    int tid = threadIdx.x;
    int wid = tid >> 5, lane = tid & 31;
    int wm = wid >> 1, wn = wid & 1;
    int gid = lane >> 2, tig = lane & 3;
    int m0 = blockIdx.y * 128, n0 = blockIdx.x * 128;

    float acc[4][8][4];
    #pragma unroll
    for (int i = 0; i < 4; i++)
        #pragma unroll
        for (int j = 0; j < 8; j++)
            #pragma unroll
            for (int c = 0; c < 4; c++) acc[i][j][c] = 0.f;

    int lrow = tid >> 2, lseg = tid & 3;

    auto issue = [&](int kc0, uint32_t bufo) {
        #pragma unroll
        for (int i = 0; i < 4; i++) {
            int row = lrow + i * 32;
            size_t ga = (size_t)(m0 + row) * K + kc0 + lseg * 8;
            size_t gb = (size_t)(n0 + row) * K + kc0 + lseg * 8;
            uint32_t so = sb + bufo + (uint32_t)(row * GT_STRIDE + lseg * 16);
            CP_ASYNC16(so + G_A, A + ga);
            CP_ASYNC16(so + G_B, B + gb);
        }
    };

    int sub = lane >> 3, rin = lane & 7;
    uint32_t aoff = (uint32_t)((wm*64 + (sub & 1)*8 + rin) * GT_STRIDE + (sub >> 1) * 16);
    uint32_t boff = (uint32_t)((wn*64 + (sub >> 1)*8 + rin) * GT_STRIDE + (sub & 1) * 16);

    int nch = K >> 5;
    issue(0, 0); CP_COMMIT();
    issue(32, GBUF); CP_COMMIT();

    for (int ch = 0; ch < nch; ch++) {
        uint32_t bufo = (uint32_t)(ch & 1) * GBUF;
        CP_WAIT1();
        __syncthreads();

        #pragma unroll
        for (int ks = 0; ks < 2; ks++) {
            uint32_t fA[4][4];
            #pragma unroll
            for (int am = 0; am < 4; am++) {
                uint32_t ad = sb + bufo + G_A + aoff + am * (16 * GT_STRIDE) + ks * 32;
                LDSM_X4(fA[am][0], fA[am][1], fA[am][2], fA[am][3], ad);
            }
            uint32_t fB[8][2];
            #pragma unroll
            for (int bg = 0; bg < 4; bg++) {
                uint32_t bd = sb + bufo + G_B + boff + bg * (16 * GT_STRIDE) + ks * 32;
                LDSM_X4(fB[2*bg][0], fB[2*bg][1], fB[2*bg+1][0], fB[2*bg+1][1], bd);
            }
            #pragma unroll
            for (int am = 0; am < 4; am++)
                #pragma unroll
                for (int nb = 0; nb < 8; nb++)
                    MMA_F16(acc[am][nb], fA[am], fB[nb]);
        }
        __syncthreads();
        if (ch + 2 < nch) issue((ch + 2) << 5, bufo);
        CP_COMMIT();
    }

    #pragma unroll
    for (int am = 0; am < 4; am++) {
        int row = m0 + wm*64 + am*16 + gid;
        #pragma unroll
        for (int nb = 0; nb < 8; nb++) {
            int col = n0 + wn*64 + nb*8 + tig*2;
            float2 bv = *(const float2*)(bias + col);
            float2 o0 = { acc[am][nb][0] + bv.x, acc[am][nb][1] + bv.y };
            float2 o1 = { acc[am][nb][2] + bv.x, acc[am][nb][3] + bv.y };
            *(float2*)(C + (size_t)row * N + col)       = o0;
            *(float2*)(C + (size_t)(row + 8) * N + col) = o1;
        }
    }
}

// ---------------- mask dtype detection ----------------
__global__ void detect_mask_kind(const void* mask)
{
    __shared__ int s_int, s_float;
    if (threadIdx.x == 0) { s_int = 1; s_float = 1; }
    __syncthreads();
    const unsigned int* w = (const unsigned int*)mask;
    int ok_i = 1, ok_f = 1;
    for (int i = threadIdx.x; i < 1024; i += blockDim.x) {
        unsigned int v = w[i];
        if (v > 1u) ok_i = 0;
        if (v != 0u && v != 0x3F800000u) ok_f = 0;
    }
    atomicAnd(&s_int, ok_i);
    atomicAnd(&s_float, ok_f);
    __syncthreads();
    if (threadIdx.x == 0) g_mask_kind = s_int ? 0 : (s_float ? 1 : 2);
}

// ---------------- mask -> fp32 addend (0 or NEGF) ----------------
__global__ void mask_prep(const void* __restrict__ mask, float* __restrict__ madd, int n4)
{
    int i = blockIdx.x * blockDim.x + threadIdx.x;
    if (i >= n4) return;
    int kind = g_mask_kind;
    float4 o;
    if (kind == 0) {
        int4 v = ((const int4*)mask)[i];
        o.x = v.x ? 0.f : NEGF; o.y = v.y ? 0.f : NEGF;
        o.z = v.z ? 0.f : NEGF; o.w = v.w ? 0.f : NEGF;
    } else if (kind == 1) {
        float4 v = ((const float4*)mask)[i];
        o.x = v.x != 0.f ? 0.f : NEGF; o.y = v.y != 0.f ? 0.f : NEGF;
        o.z = v.z != 0.f ? 0.f : NEGF; o.w = v.w != 0.f ? 0.f : NEGF;
    } else {
        uchar4 v = ((const uchar4*)mask)[i];
        o.x = v.x ? 0.f : NEGF; o.y = v.y ? 0.f : NEGF;
        o.z = v.z ? 0.f : NEGF; o.w = v.w ? 0.f : NEGF;
    }
    ((float4*)madd)[i] = o;
}

// ================ direct-pair HMMA flash: CTA = 32 i-rows x ALL 8 heads ================
// grid (T/32, B), 256 threads, warp = head. j-tiles of 32. Reads pair coalesced.
#define BI 32
#define BJ 32
#define KSR 1040                    // K/V smem row stride (512 fp16 + 8)
#define BSR 1040                    // bias row (32j*8h*4B = 1024) + 16
#define MSR 144                     // mask row (32*4B) + 16
#define FS_K 0
#define FS_V (BI*KSR)               // 33280
#define FS_B (2*BI*KSR)             // 66560
#define FS_M (FS_B + BI*BSR)        // 99840
#define FBUF (FS_M + BI*MSR)        // 104448
#define FSM_TOT (2*FBUF)            // 208896

__global__ __launch_bounds__(256, 1)
void flash_direct(const __half* __restrict__ qh, const __half* __restrict__ kh,
                  const __half* __restrict__ vh, const float* __restrict__ pair,
                  const float* __restrict__ madd, __half* __restrict__ oh)
{
    extern __shared__ __align__(16) char sm[];
    uint32_t sb = smem_u32(sm);
    int tid = threadIdx.x;
    int h = tid >> 5, lane = tid & 31;      // warp = head
    int gid = lane >> 2, tig = lane & 3;
    int sub = lane >> 3, rin = lane & 7;
    int b = blockIdx.y;
    int i0 = blockIdx.x * BI;

    // ---- stage Q tile (32 rows x 512, all heads) into buf0 FS_K, extract frags ----
    const __half* qhp = qh + (size_t)(b*TT + i0) * CC;
    #pragma unroll
    for (int u = 0; u < 8; u++) {
        int f = u * 256 + tid;               // 0..2047
        int row = f >> 6, seg = f & 63;
        *(float4*)(sm + FS_K + row*KSR + seg*16) =
            *(const float4*)(qhp + (size_t)row*CC + seg*8);
    }
    __syncthreads();
    uint32_t qf[2][4][4];                    // [m-tile][kb][regs]
    #pragma unroll
    for (int am = 0; am < 2; am++) {
        uint32_t qa = sb + FS_K +
            (uint32_t)((am*16 + (sub & 1)*8 + rin) * KSR + h*128 + (sub >> 1)*16);
        #pragma unroll
        for (int kb = 0; kb < 4; kb++)
            LDSM_X4(qf[am][kb][0], qf[am][kb][1], qf[am][kb][2], qf[am][kb][3], qa + kb*32);
    }
    __syncthreads();

    float accO[2][8][4];
    #pragma unroll
    for (int am = 0; am < 2; am++)
        #pragma unroll
        for (int nb = 0; nb < 8; nb++)
            #pragma unroll
            for (int c = 0; c < 4; c++) accO[am][nb][c] = 0.f;
    float mrow[2][2], lrow[2][2];
    #pragma unroll
    for (int am = 0; am < 2; am++) {
        mrow[am][0] = -3.0e38f; mrow[am][1] = -3.0e38f;
        lrow[am][0] = 0.f;      lrow[am][1] = 0.f;
    }

    const __half* khp = kh + (size_t)(b*TT) * CC;
    const __half* vhp = vh + (size_t)(b*TT) * CC;
    const float* pbase = pair + ((size_t)(b*TT + i0) * TT) * HH;  // + row*TT*HH + (j0)*HH
    const float* mbase = madd + (size_t)(b*TT + i0) * TT;

    auto issue_tile = [&](int jt, uint32_t bufo) {
        int j0 = jt * BJ;
        // K/V: 32 rows x 64 segs each
        #pragma unroll
        for (int u = 0; u < 8; u++) {
            int f = u * 256 + tid;
            int row = f >> 6, seg = f & 63;
            size_t g = (size_t)(j0 + row) * CC + seg * 8;
            uint32_t so = sb + bufo + (uint32_t)(row*KSR + seg*16);
            CP_ASYNC16(so + FS_K, khp + g);
            CP_ASYNC16(so + FS_V, vhp + g);
        }
        // bias (pair): 32 i-rows x 64 segs (j,h contiguous)
        #pragma unroll
        for (int u = 0; u < 8; u++) {
            int f = u * 256 + tid;
            int row = f >> 6, seg = f & 63;
            CP_ASYNC16(sb + bufo + FS_B + (uint32_t)(row*BSR + seg*16),
                       pbase + (size_t)row*TT*HH + (size_t)j0*HH + seg*4);
        }
        // mask addend: 32 i-rows x 8 segs
        {
            int row = tid >> 3, seg = tid & 7;
            CP_ASYNC16(sb + bufo + FS_M + (uint32_t)(row*MSR + seg*16),
                       mbase + (size_t)row*TT + j0 + seg*4);
        }
    };

    uint32_t kfo = (uint32_t)(((sub >> 1)*8 + rin) * KSR + h*128 + (sub & 1)*16);
    uint32_t vfo = (uint32_t)(((sub & 1)*8 + rin) * KSR + h*128 + (sub >> 1)*16);

    issue_tile(0, 0); CP_COMMIT();
    issue_tile(1, FBUF); CP_COMMIT();

    for (int jt = 0; jt < TT/BJ; jt++) {
        uint32_t bufo = (uint32_t)(jt & 1) * FBUF;
        CP_WAIT1();
        __syncthreads();

        // ---- S = Q K^T + pair + maskadd ----
        float s[2][4][4];
        #pragma unroll
        for (int am = 0; am < 2; am++) {
            int r0 = am*16 + gid;
            #pragma unroll
            for (int nb = 0; nb < 4; nb++) {
                int j = nb*8 + tig*2;
                const float* bp0 = (const float*)(sm + bufo + FS_B + r0*BSR) + j*8 + h;
                const float* bp1 = (const float*)(sm + bufo + FS_B + (r0+8)*BSR) + j*8 + h;
                const float* mp0 = (const float*)(sm + bufo + FS_M + r0*MSR) + j;
                const float* mp1 = (const float*)(sm + bufo + FS_M + (r0+8)*MSR) + j;
                s[am][nb][0] = bp0[0] + mp0[0];
                s[am][nb][1] = bp0[8] + mp0[1];
                s[am][nb][2] = bp1[0] + mp1[0];
                s[am][nb][3] = bp1[8] + mp1[1];
            }
        }
        #pragma unroll
        for (int kb = 0; kb < 4; kb++) {
            uint32_t kf[4][2];
            #pragma unroll
            for (int nb2 = 0; nb2 < 2; nb2++) {
                uint32_t ka = sb + bufo + FS_K + kfo + (uint32_t)(nb2*16*KSR + kb*32);
                LDSM_X4(kf[2*nb2][0], kf[2*nb2][1], kf[2*nb2+1][0], kf[2*nb2+1][1], ka);
            }
            #pragma unroll
            for (int am = 0; am < 2; am++)
                #pragma unroll
                for (int nb = 0; nb < 4; nb++)
                    MMA_F16(s[am][nb], qf[am][kb], kf[nb]);
        }

        // ---- online softmax (per m-tile) ----
        #pragma unroll
        for (int am = 0; am < 2; am++) {
            float mt0 = s[am][0][0], mt1 = s[am][0][2];
            #pragma unroll
            for (int nb = 0; nb < 4; nb++) {
                mt0 = fmaxf(mt0, fmaxf(s[am][nb][0], s[am][nb][1]));
                mt1 = fmaxf(mt1, fmaxf(s[am][nb][2], s[am][nb][3]));
            }
            mt0 = fmaxf(mt0, __shfl_xor_sync(0xffffffffu, mt0, 1));
            mt0 = fmaxf(mt0, __shfl_xor_sync(0xffffffffu, mt0, 2));
            mt1 = fmaxf(mt1, __shfl_xor_sync(0xffffffffu, mt1, 1));
            mt1 = fmaxf(mt1, __shfl_xor_sync(0xffffffffu, mt1, 2));
            float mn0 = fmaxf(mrow[am][0], mt0), mn1 = fmaxf(mrow[am][1], mt1);
            float c0 = fexp(mrow[am][0] - mn0), c1 = fexp(mrow[am][1] - mn1);
            lrow[am][0] *= c0; lrow[am][1] *= c1;
            #pragma unroll
            for (int nb = 0; nb < 8; nb++) {
                accO[am][nb][0] *= c0; accO[am][nb][1] *= c0;
                accO[am][nb][2] *= c1; accO[am][nb][3] *= c1;
            }
            #pragma unroll
            for (int nb = 0; nb < 4; nb++) {
                s[am][nb][0] = fexp(s[am][nb][0] - mn0);
                s[am][nb][1] = fexp(s[am][nb][1] - mn0);
                s[am][nb][2] = fexp(s[am][nb][2] - mn1);
                s[am][nb][3] = fexp(s[am][nb][3] - mn1);
                lrow[am][0] += s[am][nb][0] + s[am][nb][1];
                lrow[am][1] += s[am][nb][2] + s[am][nb][3];
            }
            mrow[am][0] = mn0; mrow[am][1] = mn1;
        }

        // ---- O += P V ----
        #pragma unroll
        for (int kb = 0; kb < 2; kb++) {        // BJ=32 -> 2 k16 blocks
            uint32_t ph[2][4];
            #pragma unroll
            for (int am = 0; am < 2; am++) {
                int ne = 2*kb, no = 2*kb + 1;
                __half2 H;
                H = __floats2half2_rn(s[am][ne][0], s[am][ne][1]); ph[am][0] = *reinterpret_cast<uint32_t*>(&H);
                H = __floats2half2_rn(s[am][ne][2], s[am][ne][3]); ph[am][1] = *reinterpret_cast<uint32_t*>(&H);
                H = __floats2half2_rn(s[am][no][0], s[am][no][1]); ph[am][2] = *reinterpret_cast<uint32_t*>(&H);
                H = __floats2half2_rn(s[am][no][2], s[am][no][3]); ph[am][3] = *reinterpret_cast<uint32_t*>(&H);
            }
            uint32_t vf[8][2];
            #pragma unroll
            for (int db2 = 0; db2 < 4; db2++) {
                uint32_t va = sb + bufo + FS_V + vfo + (uint32_t)(kb*16*KSR + db2*32);
                LDSM_X4_T(vf[2*db2][0], vf[2*db2][1], vf[2*db2+1][0], vf[2*db2+1][1], va);
            }
            #pragma unroll
            for (int am = 0; am < 2; am++)
                #pragma unroll
                for (int db = 0; db < 8; db++)
                    MMA_F16(accO[am][db], ph[am], vf[db]);
        }

        __syncthreads();
        if (jt + 2 < TT/BJ) issue_tile(jt + 2, bufo);
        CP_COMMIT();
    }

    // ---- finalize ----
    #pragma unroll
    for (int am = 0; am < 2; am++) {
        lrow[am][0] += __shfl_xor_sync(0xffffffffu, lrow[am][0], 1);
        lrow[am][0] += __shfl_xor_sync(0xffffffffu, lrow[am][0], 2);
        lrow[am][1] += __shfl_xor_sync(0xffffffffu, lrow[am][1], 1);
        lrow[am][1] += __shfl_xor_sync(0xffffffffu, lrow[am][1], 2);
        float inv0 = 1.f / lrow[am][0], inv1 = 1.f / lrow[am][1];

        size_t r0 = (size_t)(b*TT + i0 + am*16 + gid) * CC + h * DD;
        size_t r1 = r0 + 8 * CC;
        #pragma unroll
        for (int nb = 0; nb < 8; nb++) {
            int col = nb*8 + tig*2;
            *(__half2*)(oh + r0 + col) = __floats2half2_rn(accO[am][nb][0]*inv0, accO[am][nb][1]*inv0);
            *(__half2*)(oh + r1 + col) = __floats2half2_rn(accO[am][nb][2]*inv1, accO[am][nb][3]*inv1);
        }
    }
}

// ---------------- launch ----------------
extern "C" void kernel_launch(void* const* d_in, const int* in_sizes, int n_in,
                              void* d_out, int out_size)
{
    const float* x      = (const float*)d_in[0];
    const float* pair   = (const float*)d_in[1];
    const void*  mask   = d_in[2];
    const float* norm_w = (const float*)d_in[3];
    const float* norm_b = (const float*)d_in[4];
    const float* qkv_w  = (const float*)d_in[5];
    const float* qkv_b  = (const float*)d_in[6];
    const float* qln_w  = (const float*)d_in[7];
    const float* qln_b  = (const float*)d_in[8];
    const float* kln_w  = (const float*)d_in[9];
    const float* kln_b  = (const float*)d_in[10];
    const float* proj_w = (const float*)d_in[11];
    const float* proj_b = (const float*)d_in[12];
    float* out = (float*)d_out;

    float *qkvp, *madd;
    __half *ah, *wh, *wp, *qh, *kh, *vh;
    cudaGetSymbolAddress((void**)&qkvp, g_qkv);
    cudaGetSymbolAddress((void**)&madd, g_maskadd);
    cudaGetSymbolAddress((void**)&ah, g_ah);
    cudaGetSymbolAddress((void**)&wh, g_wh);
    cudaGetSymbolAddress((void**)&wp, g_wp);
    cudaGetSymbolAddress((void**)&qh, g_qh);
    cudaGetSymbolAddress((void**)&kh, g_kh);
    cudaGetSymbolAddress((void**)&vh, g_vh);

    cudaFuncSetAttribute(flash_direct, cudaFuncAttributeMaxDynamicSharedMemorySize, FSM_TOT);
    cudaFuncSetAttribute(gemm_tc16, cudaFuncAttributeMaxDynamicSharedMemorySize, GSMEM);

    cudaStream_t s0 = 0;
    cudaStream_t s2 = g_hx.s2;

    // ---- fork: branch B (mask prep + proj weight cvt) on s2 ----
    cudaEventRecord(g_hx.evFork, s0);
    cudaStreamWaitEvent(s2, g_hx.evFork, 0);
    detect_mask_kind<<<1, 256, 0, s2>>>(mask);
    mask_prep<<<(BB*TT*TT/4 + 255)/256, 256, 0, s2>>>(mask, madd, BB*TT*TT/4);
    cvt_kernel<<<(CC*CC/4 + 255)/256, 256, 0, s2>>>(proj_w, wp, CC*CC/4);
    cudaEventRecord(g_hx.evJoin, s2);

    // branch A: QKV path on s0
    ln_h_kernel<<<NROWS, 128, 0, s0>>>(x, norm_w, norm_b, ah);
    cvt_kernel<<<(C3*CC/4 + 255)/256, 256, 0, s0>>>(qkv_w, wh, C3*CC/4);
    gemm_tc16<<<dim3(C3/128, NROWS/128), 128, GSMEM, s0>>>(ah, wh, qkv_b, qkvp, C3, CC);
    qkv_post<<<NROWS, 128, 0, s0>>>(qkvp, qln_w, qln_b, kln_w, kln_b);

    // ---- join: flash needs both branches ----
    cudaStreamWaitEvent(s0, g_hx.evJoin, 0);
    flash_direct<<<dim3(TT/BI, BB), 256, FSM_TOT, s0>>>(qh, kh, vh, pair, madd, ah);
    gemm_tc16<<<dim3(CC/128, NROWS/128), 128, GSMEM, s0>>>(ah, wp, proj_b, out, CC, CC);
}